// round 1
// baseline (speedup 1.0000x reference)
#include <cuda_runtime.h>

#define BATCH 16
#define CIN   256
#define HWN   4096
#define DHEAD 32
#define NHEAD 8
#define MQ    256

// ---------------- scratch (device globals: no allocation allowed) -----------
__device__ float g_KV[BATCH * DHEAD * HWN];     // 8.4 MB  (bn'd kv)
__device__ float g_Q [BATCH * MQ * HWN];        // 67 MB   (bn'd q)
__device__ float g_A [BATCH * MQ * HWN];        // 67 MB   (relu(attended))
__device__ float g_ctxT[BATCH * DHEAD * DHEAD]; // ctxT[d][e] per batch
__device__ float g_rm[BATCH * DHEAD];
__device__ float g_rs[BATCH * DHEAD];
__device__ float g_Wq [MQ * CIN];  __device__ float g_bq [MQ];
__device__ float g_Wkv[DHEAD * CIN]; __device__ float g_bkv[DHEAD];
__device__ float g_Wp [CIN * MQ];  __device__ float g_bp [CIN];

// ---------------- packed f32x2 helpers --------------------------------------
#define PACKF2(u, lo, hi) asm("mov.b64 %0, {%1, %2};" : "=l"(u) : "f"(lo), "f"(hi))
#define UNPACKF2(lo, hi, u) asm("mov.b64 {%0, %1}, %2;" : "=f"(lo), "=f"(hi) : "l"(u))
#define FMAF2(c, a, b) asm("fma.rn.f32x2 %0, %1, %2, %0;" : "+l"(c) : "l"(a), "l"(b))

// ---------------- 1) fold BN into weights -----------------------------------
__global__ void fold_kernel(
    const float* __restrict__ Wq, const float* __restrict__ gq, const float* __restrict__ bq,
    const float* __restrict__ mq, const float* __restrict__ vq,
    const float* __restrict__ Wkv, const float* __restrict__ gkv, const float* __restrict__ bkv,
    const float* __restrict__ mkv, const float* __restrict__ vkv,
    const float* __restrict__ Wp, const float* __restrict__ gp, const float* __restrict__ bp,
    const float* __restrict__ mp, const float* __restrict__ vp)
{
    int t = blockIdx.x * blockDim.x + threadIdx.x;
    int stride = gridDim.x * blockDim.x;
    const float eps = 1e-5f;
    for (int i = t; i < MQ * CIN; i += stride) {
        int o = i / CIN; float s = gq[o] * rsqrtf(vq[o] + eps);
        g_Wq[i] = Wq[i] * s;
    }
    for (int i = t; i < DHEAD * CIN; i += stride) {
        int o = i / CIN; float s = gkv[o] * rsqrtf(vkv[o] + eps);
        g_Wkv[i] = Wkv[i] * s;
    }
    for (int i = t; i < CIN * MQ; i += stride) {
        int o = i / MQ; float s = gp[o] * rsqrtf(vp[o] + eps);
        g_Wp[i] = Wp[i] * s;
    }
    for (int i = t; i < MQ; i += stride) {
        float s = gq[i] * rsqrtf(vq[i] + eps); g_bq[i] = bq[i] - mq[i] * s;
    }
    for (int i = t; i < DHEAD; i += stride) {
        float s = gkv[i] * rsqrtf(vkv[i] + eps); g_bkv[i] = bkv[i] - mkv[i] * s;
    }
    for (int i = t; i < CIN; i += stride) {
        float s = gp[i] * rsqrtf(vp[i] + eps); g_bp[i] = bp[i] - mp[i] * s;
    }
}

// ---------------- 2) KV projection: g_KV[b][d][n] = Wkv_f @ x + b -----------
// grid (HWN/256, BATCH), 256 threads. Whole folded Wkv (32x256) lives in smem
// transposed as Ws[k][m].
__global__ __launch_bounds__(256) void kv_kernel(const float* __restrict__ X)
{
    __shared__ float Ws[CIN][DHEAD];   // 32 KB
    __shared__ float bs[DHEAD];
    int t = threadIdx.x;
    for (int i = t; i < DHEAD * CIN; i += 256) {
        int m = i / CIN, k = i % CIN;
        Ws[k][m] = g_Wkv[i];
    }
    if (t < DHEAD) bs[t] = g_bkv[t];
    __syncthreads();

    int b = blockIdx.y;
    int n = blockIdx.x * 256 + t;
    const float* x = X + (size_t)b * CIN * HWN + n;

    float acc[DHEAD];
#pragma unroll
    for (int m = 0; m < DHEAD; m++) acc[m] = bs[m];

#pragma unroll 4
    for (int k = 0; k < CIN; k++) {
        float xv = x[(size_t)k * HWN];
        const float4* wr = reinterpret_cast<const float4*>(&Ws[k][0]);
#pragma unroll
        for (int j = 0; j < 8; j++) {
            float4 w = wr[j];
            acc[j*4+0] += w.x * xv;
            acc[j*4+1] += w.y * xv;
            acc[j*4+2] += w.z * xv;
            acc[j*4+3] += w.w * xv;
        }
    }
    float* y = g_KV + (size_t)b * DHEAD * HWN + n;
#pragma unroll
    for (int m = 0; m < DHEAD; m++) y[(size_t)m * HWN] = acc[m];
}

// ---------------- 3) row softmax stats over spatial dim + zero ctxT ---------
// grid BATCH, 1024 threads (32 warps, one warp per kv row)
__global__ __launch_bounds__(1024) void rowstats_kernel()
{
    int b = blockIdx.x;
    int t = threadIdx.x;
    g_ctxT[b * DHEAD * DHEAD + t] = 0.0f;   // 1024 == blockDim

    int w = t >> 5, l = t & 31;
    const float* row = g_KV + (size_t)b * DHEAD * HWN + (size_t)w * HWN;

    float mx = -1e30f;
    for (int n = l; n < HWN; n += 32) mx = fmaxf(mx, row[n]);
#pragma unroll
    for (int o = 16; o > 0; o >>= 1) mx = fmaxf(mx, __shfl_xor_sync(0xffffffffu, mx, o));

    float s = 0.0f;
    for (int n = l; n < HWN; n += 32) s += __expf(row[n] - mx);
#pragma unroll
    for (int o = 16; o > 0; o >>= 1) s += __shfl_xor_sync(0xffffffffu, s, o);

    if (l == 0) { g_rm[b * DHEAD + w] = mx; g_rs[b * DHEAD + w] = s; }
}

// ---------------- 4) ctxT[d][e] = sum_n softmax_row_e(kv)[n] * kv[d][n] -----
// grid (8 n-splits, BATCH), 256 threads; partial sums via atomicAdd.
__global__ __launch_bounds__(256) void ctx_kernel()
{
    __shared__ float kvs[DHEAD][129];
    __shared__ float ps [DHEAD][129];
    __shared__ float ms[DHEAD], ssi[DHEAD];

    int b = blockIdx.y;
    int t = threadIdx.x;
    if (t < DHEAD) { ms[t] = g_rm[b * DHEAD + t]; ssi[t] = 1.0f / g_rs[b * DHEAD + t]; }

    int d = t & 31;
    int e0 = (t >> 5) * 4;
    float acc[4] = {0.f, 0.f, 0.f, 0.f};
    int nbase = blockIdx.x * 512;

    for (int nt = 0; nt < 4; nt++) {
        int n0 = nbase + nt * 128;
        __syncthreads();
        for (int i = t; i < DHEAD * 128; i += 256) {
            int r = i >> 7, nn = i & 127;
            float v = g_KV[(size_t)b * DHEAD * HWN + (size_t)r * HWN + n0 + nn];
            kvs[r][nn] = v;
            ps [r][nn] = __expf(v - ms[r]) * ssi[r];
        }
        __syncthreads();
#pragma unroll 4
        for (int nn = 0; nn < 128; nn++) {
            float kd = kvs[d][nn];
#pragma unroll
            for (int j = 0; j < 4; j++) acc[j] += ps[e0 + j][nn] * kd;
        }
    }
#pragma unroll
    for (int j = 0; j < 4; j++)
        atomicAdd(&g_ctxT[b * DHEAD * DHEAD + d * DHEAD + (e0 + j)], acc[j]);
}

// ---------------- 5) big GEMM: Y[b] = Wf(256x256) @ X[b](256x4096) + bias ---
// mode 0: X = input param, Y = g_Q, W = g_Wq       (Q projection)
// mode 1: X = g_A,         Y = out param, W = g_Wp (output projection)
// 128x128 block tile, BK=32, 8x8 per thread, f32x2 FFMA2 math.
__global__ __launch_bounds__(256, 2) void gemm_kernel(
    int mode, const float* __restrict__ Xparam, float* __restrict__ Yparam)
{
    __shared__ float Wst[32][132];  // transposed W tile [k][m]
    __shared__ float Xs [32][128];

    const float* Wf   = mode ? (const float*)g_Wp : (const float*)g_Wq;
    const float* bias = mode ? (const float*)g_bp : (const float*)g_bq;
    const float* X    = mode ? (const float*)g_A  : Xparam;
    float*       Y    = mode ? Yparam             : (float*)g_Q;

    int t  = threadIdx.x;
    int b  = blockIdx.z;
    int m0 = blockIdx.y * 128;
    int n0 = blockIdx.x * 128;
    const float* Xb = X + (size_t)b * CIN * HWN;

    unsigned long long acc[8][4] = {};

    int tm = t >> 4, tn = t & 15;

    for (int k0 = 0; k0 < CIN; k0 += 32) {
        // load W tile (128 m x 32 k), store transposed
#pragma unroll
        for (int i = 0; i < 4; i++) {
            int s = t + i * 256;
            int m = s >> 3, kq = s & 7;
            float4 w = *reinterpret_cast<const float4*>(&Wf[(size_t)(m0 + m) * CIN + k0 + kq * 4]);
            Wst[kq * 4 + 0][m] = w.x;
            Wst[kq * 4 + 1][m] = w.y;
            Wst[kq * 4 + 2][m] = w.z;
            Wst[kq * 4 + 3][m] = w.w;
        }
        // load X tile (32 k x 128 n)
#pragma unroll
        for (int i = 0; i < 4; i++) {
            int s = t + i * 256;
            int k = s >> 5, nq = s & 31;
            *reinterpret_cast<float4*>(&Xs[k][nq * 4]) =
                *reinterpret_cast<const float4*>(&Xb[(size_t)(k0 + k) * HWN + n0 + nq * 4]);
        }
        __syncthreads();

#pragma unroll
        for (int k = 0; k < 32; k++) {
            float4 a0 = *reinterpret_cast<const float4*>(&Wst[k][tm * 8]);
            float4 a1 = *reinterpret_cast<const float4*>(&Wst[k][tm * 8 + 4]);
            const unsigned long long* bsrc =
                reinterpret_cast<const unsigned long long*>(&Xs[k][tn * 8]);
            unsigned long long bp0 = bsrc[0], bp1 = bsrc[1], bp2 = bsrc[2], bp3 = bsrc[3];
            float av[8] = {a0.x, a0.y, a0.z, a0.w, a1.x, a1.y, a1.z, a1.w};
#pragma unroll
            for (int i = 0; i < 8; i++) {
                unsigned long long ap;
                PACKF2(ap, av[i], av[i]);
                FMAF2(acc[i][0], ap, bp0);
                FMAF2(acc[i][1], ap, bp1);
                FMAF2(acc[i][2], ap, bp2);
                FMAF2(acc[i][3], ap, bp3);
            }
        }
        __syncthreads();
    }

    float* Yb = Y + (size_t)b * MQ * HWN;
#pragma unroll
    for (int i = 0; i < 8; i++) {
        int m = m0 + tm * 8 + i;
        float bb = bias[m];
        float o[8];
#pragma unroll
        for (int j = 0; j < 4; j++) {
            float lo, hi;
            UNPACKF2(lo, hi, acc[i][j]);
            o[j * 2] = lo + bb; o[j * 2 + 1] = hi + bb;
        }
        float4* dst = reinterpret_cast<float4*>(&Yb[(size_t)m * HWN + n0 + tn * 8]);
        dst[0] = make_float4(o[0], o[1], o[2], o[3]);
        dst[1] = make_float4(o[4], o[5], o[6], o[7]);
    }
}

// ---------------- 6) per-position head softmax + ctxT matvec + relu ---------
// grid (HWN/32, BATCH), block (32, 8): thread = (position lane, head)
__global__ __launch_bounds__(256) void attn_kernel()
{
    __shared__ float csT[DHEAD * DHEAD];   // csT[e][d] = ctxT[d][e]
    int b = blockIdx.y;
    int t = threadIdx.y * 32 + threadIdx.x;
    for (int i = t; i < DHEAD * DHEAD; i += 256) {
        int d = i >> 5, e = i & 31;
        csT[e * DHEAD + d] = g_ctxT[b * DHEAD * DHEAD + i];
    }
    __syncthreads();

    int n = blockIdx.x * 32 + threadIdx.x;
    int h = threadIdx.y;
    const float* q = g_Q + (size_t)b * MQ * HWN + (size_t)h * DHEAD * HWN + n;

    float qv[DHEAD];
#pragma unroll
    for (int e = 0; e < DHEAD; e++) qv[e] = q[(size_t)e * HWN];

    float mx = -1e30f;
#pragma unroll
    for (int e = 0; e < DHEAD; e++) mx = fmaxf(mx, qv[e]);
    float s = 0.0f;
#pragma unroll
    for (int e = 0; e < DHEAD; e++) { qv[e] = __expf(qv[e] - mx); s += qv[e]; }
    float inv = 1.0f / s;
#pragma unroll
    for (int e = 0; e < DHEAD; e++) qv[e] *= inv;

    float att[DHEAD];
#pragma unroll
    for (int d = 0; d < DHEAD; d++) att[d] = 0.0f;

#pragma unroll
    for (int e = 0; e < DHEAD; e++) {
        float qe = qv[e];
        const float4* row = reinterpret_cast<const float4*>(&csT[e * DHEAD]);
#pragma unroll
        for (int j = 0; j < 8; j++) {
            float4 c4 = row[j];
            att[j*4+0] += c4.x * qe;
            att[j*4+1] += c4.y * qe;
            att[j*4+2] += c4.z * qe;
            att[j*4+3] += c4.w * qe;
        }
    }

    float* a = g_A + (size_t)b * MQ * HWN + (size_t)h * DHEAD * HWN + n;
#pragma unroll
    for (int d = 0; d < DHEAD; d++) a[(size_t)d * HWN] = fmaxf(att[d], 0.0f);
}

// ---------------- launch -----------------------------------------------------
extern "C" void kernel_launch(void* const* d_in, const int* in_sizes, int n_in,
                              void* d_out, int out_size)
{
    const float* input = (const float*)d_in[0];
    // d_in[1] (key_v_input_reduction) unused by reference
    const float* Wq  = (const float*)d_in[2];
    const float* gq  = (const float*)d_in[3];
    const float* bq  = (const float*)d_in[4];
    const float* mq  = (const float*)d_in[5];
    const float* vq  = (const float*)d_in[6];
    const float* Wkv = (const float*)d_in[7];
    const float* gkv = (const float*)d_in[8];
    const float* bkv = (const float*)d_in[9];
    const float* mkv = (const float*)d_in[10];
    const float* vkv = (const float*)d_in[11];
    const float* Wp  = (const float*)d_in[12];
    const float* gp  = (const float*)d_in[13];
    const float* bp  = (const float*)d_in[14];
    const float* mp  = (const float*)d_in[15];
    const float* vp  = (const float*)d_in[16];
    float* out = (float*)d_out;

    fold_kernel<<<64, 256>>>(Wq, gq, bq, mq, vq,
                             Wkv, gkv, bkv, mkv, vkv,
                             Wp, gp, bp, mp, vp);
    kv_kernel<<<dim3(HWN / 256, BATCH), 256>>>(input);
    rowstats_kernel<<<BATCH, 1024>>>();
    ctx_kernel<<<dim3(8, BATCH), 256>>>();
    gemm_kernel<<<dim3(HWN / 128, 2, BATCH), 256>>>(0, input, nullptr);
    attn_kernel<<<dim3(HWN / 32, BATCH), dim3(32, 8)>>>();
    gemm_kernel<<<dim3(HWN / 128, 2, BATCH), 256>>>(1, nullptr, out);
}

// round 4
// speedup vs baseline: 1.6578x; 1.6578x over previous
#include <cuda_runtime.h>
#include <cuda_bf16.h>
#include <cstdint>

#define BATCH 16
#define CIN   256
#define HWN   4096
#define DHEAD 32
#define NHEAD 8
#define MQ    256

// ---------------- scratch (device globals) -----------------------------------
__device__ float g_KV[BATCH * DHEAD * HWN];
__device__ float g_Q [BATCH * MQ * HWN];
__device__ float g_ctxT[BATCH * DHEAD * DHEAD];
__device__ float g_rm[BATCH * DHEAD];
__device__ float g_rs[BATCH * DHEAD];
__device__ float g_Wkv[DHEAD * CIN]; __device__ float g_bkv[DHEAD];
__device__ float g_bq [MQ];          __device__ float g_bp [CIN];
// folded weights as bf16 hi/lo planes, [mode][m*256+k] row-major
__device__ __nv_bfloat16 g_WH[2][MQ * CIN];
__device__ __nv_bfloat16 g_WL[2][MQ * CIN];
// relu(attended) as bf16 hi/lo planes, [b][k][n] row-major
__device__ __nv_bfloat16 g_XH[(size_t)BATCH * MQ * HWN];
__device__ __nv_bfloat16 g_XL[(size_t)BATCH * MQ * HWN];

// ---------------- f32x2 helpers (kv kernel) -----------------------------------
#define PACKF2(u, lo, hi) asm("mov.b64 %0, {%1, %2};" : "=l"(u) : "f"(lo), "f"(hi))
#define UNPACKF2(lo, hi, u) asm("mov.b64 {%0, %1}, %2;" : "=f"(lo), "=f"(hi) : "l"(u))
#define FMAF2(c, a, b) asm("fma.rn.f32x2 %0, %1, %2, %0;" : "+l"(c) : "l"(a), "l"(b))

// ---------------- mma helpers ---------------------------------------------------
__device__ __forceinline__ void ldsm4(uint32_t* r, uint32_t addr) {
    asm volatile("ldmatrix.sync.aligned.m8n8.x4.shared.b16 {%0,%1,%2,%3}, [%4];\n"
        : "=r"(r[0]), "=r"(r[1]), "=r"(r[2]), "=r"(r[3]) : "r"(addr));
}
__device__ __forceinline__ void ldsm4t(uint32_t* r, uint32_t addr) {
    asm volatile("ldmatrix.sync.aligned.m8n8.x4.trans.shared.b16 {%0,%1,%2,%3}, [%4];\n"
        : "=r"(r[0]), "=r"(r[1]), "=r"(r[2]), "=r"(r[3]) : "r"(addr));
}
__device__ __forceinline__ void mma_bf16(float* c, const uint32_t* a,
                                         uint32_t b0, uint32_t b1) {
    asm volatile(
        "mma.sync.aligned.m16n8k16.row.col.f32.bf16.bf16.f32 "
        "{%0,%1,%2,%3}, {%4,%5,%6,%7}, {%8,%9}, {%0,%1,%2,%3};\n"
        : "+f"(c[0]), "+f"(c[1]), "+f"(c[2]), "+f"(c[3])
        : "r"(a[0]), "r"(a[1]), "r"(a[2]), "r"(a[3]), "r"(b0), "r"(b1));
}
__device__ __forceinline__ uint32_t pack_bf2(__nv_bfloat16 a, __nv_bfloat16 b) {
    return (uint32_t)__bfloat16_as_ushort(a) | ((uint32_t)__bfloat16_as_ushort(b) << 16);
}

// ---------------- 1) fold BN + build bf16 hi/lo weight planes ------------------
__global__ void fold_kernel(
    const float* __restrict__ Wq, const float* __restrict__ gq, const float* __restrict__ bq,
    const float* __restrict__ mq, const float* __restrict__ vq,
    const float* __restrict__ Wkv, const float* __restrict__ gkv, const float* __restrict__ bkv,
    const float* __restrict__ mkv, const float* __restrict__ vkv,
    const float* __restrict__ Wp, const float* __restrict__ gp, const float* __restrict__ bp,
    const float* __restrict__ mp, const float* __restrict__ vp)
{
    int t = blockIdx.x * blockDim.x + threadIdx.x;
    int stride = gridDim.x * blockDim.x;
    const float eps = 1e-5f;
    for (int i = t; i < MQ; i += stride) {
        float s = gq[i] * rsqrtf(vq[i] + eps); g_bq[i] = bq[i] - mq[i] * s;
    }
    for (int i = t; i < CIN; i += stride) {
        float s = gp[i] * rsqrtf(vp[i] + eps); g_bp[i] = bp[i] - mp[i] * s;
    }
    for (int i = t; i < DHEAD; i += stride) {
        float s = gkv[i] * rsqrtf(vkv[i] + eps); g_bkv[i] = bkv[i] - mkv[i] * s;
    }
    for (int i = t; i < DHEAD * CIN; i += stride) {
        int o = i / CIN; g_Wkv[i] = Wkv[i] * gkv[o] * rsqrtf(vkv[o] + eps);
    }
    for (int i = t; i < MQ * CIN; i += stride) {
        int m = i >> 8;
        {
            float s = gq[m] * rsqrtf(vq[m] + eps);
            float w = Wq[i] * s;
            __nv_bfloat16 h = __float2bfloat16_rn(w);
            g_WH[0][i] = h;
            g_WL[0][i] = __float2bfloat16_rn(w - __bfloat162float(h));
        }
        {
            float s = gp[m] * rsqrtf(vp[m] + eps);
            float w = Wp[i] * s;
            __nv_bfloat16 h = __float2bfloat16_rn(w);
            g_WH[1][i] = h;
            g_WL[1][i] = __float2bfloat16_rn(w - __bfloat162float(h));
        }
    }
}

// ---------------- 2) KV projection ----------------------------------------------
__global__ __launch_bounds__(256) void kv_kernel(const float* __restrict__ X)
{
    __shared__ __align__(16) float Ws[CIN][DHEAD];
    __shared__ float bs[DHEAD];
    int t = threadIdx.x;
    for (int i = t; i < DHEAD * CIN; i += 256) {
        int m = i / CIN, k = i % CIN;
        Ws[k][m] = g_Wkv[i];
    }
    if (t < DHEAD) bs[t] = g_bkv[t];
    __syncthreads();

    int b = blockIdx.y;
    int n = blockIdx.x * 256 + t;
    const float* x = X + (size_t)b * CIN * HWN + n;

    unsigned long long acc[16];
#pragma unroll
    for (int j = 0; j < 16; j++) PACKF2(acc[j], bs[2 * j], bs[2 * j + 1]);

#pragma unroll 4
    for (int k = 0; k < CIN; k++) {
        float xv = x[(size_t)k * HWN];
        unsigned long long xp; PACKF2(xp, xv, xv);
        const ulonglong2* wr = reinterpret_cast<const ulonglong2*>(&Ws[k][0]);
#pragma unroll
        for (int j = 0; j < 8; j++) {
            ulonglong2 w = wr[j];
            FMAF2(acc[2 * j],     w.x, xp);
            FMAF2(acc[2 * j + 1], w.y, xp);
        }
    }
    float* y = g_KV + (size_t)b * DHEAD * HWN + n;
#pragma unroll
    for (int j = 0; j < 16; j++) {
        float lo, hi; UNPACKF2(lo, hi, acc[j]);
        y[(size_t)(2 * j) * HWN] = lo;
        y[(size_t)(2 * j + 1) * HWN] = hi;
    }
}

// ---------------- 3) row softmax stats + zero ctxT -------------------------------
__global__ __launch_bounds__(256) void rowstats_kernel()
{
    __shared__ float red[8];
    int d = blockIdx.x, b = blockIdx.y, t = threadIdx.x;
    int w = t >> 5, l = t & 31;
    if (t < 32) g_ctxT[b * 1024 + d * 32 + t] = 0.0f;
    const float* row = g_KV + ((size_t)b * DHEAD + d) * HWN;

    float mx = -1e30f;
    for (int n = t; n < HWN; n += 256) mx = fmaxf(mx, row[n]);
#pragma unroll
    for (int o = 16; o > 0; o >>= 1) mx = fmaxf(mx, __shfl_xor_sync(~0u, mx, o));
    if (l == 0) red[w] = mx;
    __syncthreads();
    mx = red[0];
#pragma unroll
    for (int j = 1; j < 8; j++) mx = fmaxf(mx, red[j]);
    __syncthreads();

    float s = 0.0f;
    for (int n = t; n < HWN; n += 256) s += __expf(row[n] - mx);
#pragma unroll
    for (int o = 16; o > 0; o >>= 1) s += __shfl_xor_sync(~0u, s, o);
    if (l == 0) red[w] = s;
    __syncthreads();
    if (t == 0) {
        float tot = 0.0f;
#pragma unroll
        for (int j = 0; j < 8; j++) tot += red[j];
        g_rm[b * DHEAD + d] = mx;
        g_rs[b * DHEAD + d] = tot;
    }
}

// ---------------- 4) ctxT ----------------------------------------------------------
__global__ __launch_bounds__(256) void ctx_kernel()
{
    __shared__ float kvs[DHEAD][129];
    __shared__ float ps [DHEAD][129];
    __shared__ float ms[DHEAD], ssi[DHEAD];

    int b = blockIdx.y, t = threadIdx.x;
    if (t < DHEAD) { ms[t] = g_rm[b * DHEAD + t]; ssi[t] = 1.0f / g_rs[b * DHEAD + t]; }
    __syncthreads();

    int n0 = blockIdx.x * 128;
    for (int i = t; i < DHEAD * 128; i += 256) {
        int r = i >> 7, nn = i & 127;
        float v = g_KV[((size_t)b * DHEAD + r) * HWN + n0 + nn];
        kvs[r][nn] = v;
        ps [r][nn] = __expf(v - ms[r]) * ssi[r];
    }
    __syncthreads();

    int d = t & 31, e0 = (t >> 5) * 4;
    float acc[4] = {0.f, 0.f, 0.f, 0.f};
#pragma unroll 4
    for (int nn = 0; nn < 128; nn++) {
        float kd = kvs[d][nn];
#pragma unroll
        for (int j = 0; j < 4; j++) acc[j] += ps[e0 + j][nn] * kd;
    }
#pragma unroll
    for (int j = 0; j < 4; j++)
        atomicAdd(&g_ctxT[b * 1024 + d * 32 + (e0 + j)], acc[j]);
}

// ---------------- 5) bf16 mma.sync GEMM: Y = W(256x256) @ X(256x4096) + bias ------
// mode 0: B from fp32 input (converted to hi/lo in-kernel), Y = g_Q
// mode 1: B from g_XH/g_XL bf16 planes,                     Y = d_out
// CTA: 256 thr, tile M128 x N128, K-chunks of 64. 3-pass split accumulate.
#define WH_OFF   0
#define WL_OFF   18432
#define XH_OFF   36864
#define XL_OFF   54272
#define BIAS_OFF 71680
#define GSMEM    72192

__global__ void __launch_bounds__(256, 2) mma_gemm_kernel(
    int mode, const float* __restrict__ Xf, float* __restrict__ Yext)
{
    extern __shared__ __align__(16) char smem[];
    __nv_bfloat16* sWh = reinterpret_cast<__nv_bfloat16*>(smem + WH_OFF);
    __nv_bfloat16* sWl = reinterpret_cast<__nv_bfloat16*>(smem + WL_OFF);
    __nv_bfloat16* sXh = reinterpret_cast<__nv_bfloat16*>(smem + XH_OFF);
    __nv_bfloat16* sXl = reinterpret_cast<__nv_bfloat16*>(smem + XL_OFF);
    float* sBias = reinterpret_cast<float*>(smem + BIAS_OFF);
    uint32_t sb = (uint32_t)__cvta_generic_to_shared(smem);

    int t = threadIdx.x, lane = t & 31, wid = t >> 5;
    int wm = wid & 3, wn = wid >> 2;
    int nt = blockIdx.x, mt = blockIdx.y, b = blockIdx.z;
    int m0 = mt * 128, n0 = nt * 128;

    if (t < 128) sBias[t] = (mode ? g_bp : g_bq)[m0 + t];

    const __nv_bfloat16* WH = g_WH[mode];
    const __nv_bfloat16* WL = g_WL[mode];
    float* Yg = mode ? Yext : g_Q;

    float acc[2][8][4];
#pragma unroll
    for (int i = 0; i < 2; i++)
#pragma unroll
        for (int j = 0; j < 8; j++)
#pragma unroll
            for (int k = 0; k < 4; k++) acc[i][j][k] = 0.0f;

    for (int c = 0; c < 4; c++) {
        int k0 = c * 64;
        // ---- W tiles: 128 rows x 64 halves, padded stride 72 ----
#pragma unroll
        for (int i = 0; i < 4; i++) {
            int j = t + i * 256;
            int row = j >> 3, seg = j & 7;
            size_t go = (size_t)(m0 + row) * CIN + k0 + seg * 8;
            *reinterpret_cast<uint4*>(sWh + row * 72 + seg * 8) =
                *reinterpret_cast<const uint4*>(WH + go);
            *reinterpret_cast<uint4*>(sWl + row * 72 + seg * 8) =
                *reinterpret_cast<const uint4*>(WL + go);
        }
        // ---- X tiles: 64 rows x 128 halves, padded stride 136 ----
        if (mode == 0) {
#pragma unroll
            for (int i = 0; i < 8; i++) {
                int j = t + i * 256;           // 2048 items: k(0..63) x seg(0..31)
                int k = j >> 5, seg = j & 31;
                float4 v = *reinterpret_cast<const float4*>(
                    Xf + ((size_t)b * CIN + k0 + k) * HWN + n0 + seg * 4);
                __nv_bfloat16 h0 = __float2bfloat16_rn(v.x);
                __nv_bfloat16 h1 = __float2bfloat16_rn(v.y);
                __nv_bfloat16 h2 = __float2bfloat16_rn(v.z);
                __nv_bfloat16 h3 = __float2bfloat16_rn(v.w);
                __nv_bfloat16 l0 = __float2bfloat16_rn(v.x - __bfloat162float(h0));
                __nv_bfloat16 l1 = __float2bfloat16_rn(v.y - __bfloat162float(h1));
                __nv_bfloat16 l2 = __float2bfloat16_rn(v.z - __bfloat162float(h2));
                __nv_bfloat16 l3 = __float2bfloat16_rn(v.w - __bfloat162float(h3));
                uint32_t* dh = reinterpret_cast<uint32_t*>(sXh + k * 136 + seg * 4);
                uint32_t* dl = reinterpret_cast<uint32_t*>(sXl + k * 136 + seg * 4);
                dh[0] = pack_bf2(h0, h1); dh[1] = pack_bf2(h2, h3);
                dl[0] = pack_bf2(l0, l1); dl[1] = pack_bf2(l2, l3);
            }
        } else {
#pragma unroll
            for (int i = 0; i < 4; i++) {      // FIX: 1024 items, k(0..63) x seg(0..15)
                int j = t + i * 256;
                int k = j >> 4, seg = j & 15;
                size_t go = ((size_t)b * MQ + k0 + k) * HWN + n0 + seg * 8;
                *reinterpret_cast<uint4*>(sXh + k * 136 + seg * 8) =
                    *reinterpret_cast<const uint4*>(g_XH + go);
                *reinterpret_cast<uint4*>(sXl + k * 136 + seg * 8) =
                    *reinterpret_cast<const uint4*>(g_XL + go);
            }
        }
        __syncthreads();

#pragma unroll
        for (int ks = 0; ks < 4; ks++) {
            int kk = ks * 16;
            uint32_t ah[2][4], al[2][4];
#pragma unroll
            for (int mf = 0; mf < 2; mf++) {
                int row = wm * 32 + mf * 16 + (lane & 15);
                int col = kk + (lane >> 4) * 8;
                uint32_t a_addr = sb + WH_OFF + (uint32_t)(row * 72 + col) * 2;
                ldsm4(ah[mf], a_addr);
                ldsm4(al[mf], a_addr + (WL_OFF - WH_OFF));
            }
#pragma unroll
            for (int r = 0; r < 4; r++) {
                int kr = kk + (lane & 15);
                int coln = wn * 64 + r * 16 + (lane >> 4) * 8;
                uint32_t b_addr = sb + XH_OFF + (uint32_t)(kr * 136 + coln) * 2;
                uint32_t bh[4], bl[4];
                ldsm4t(bh, b_addr);
                ldsm4t(bl, b_addr + (XL_OFF - XH_OFF));
#pragma unroll
                for (int mf = 0; mf < 2; mf++) {
                    mma_bf16(acc[mf][r * 2],     ah[mf], bh[0], bh[1]);
                    mma_bf16(acc[mf][r * 2 + 1], ah[mf], bh[2], bh[3]);
                    mma_bf16(acc[mf][r * 2],     ah[mf], bl[0], bl[1]);
                    mma_bf16(acc[mf][r * 2 + 1], ah[mf], bl[2], bl[3]);
                    mma_bf16(acc[mf][r * 2],     al[mf], bh[0], bh[1]);
                    mma_bf16(acc[mf][r * 2 + 1], al[mf], bh[2], bh[3]);
                }
            }
        }
        __syncthreads();
    }

    // ---- epilogue: stage through smem (stride 132) for coalesced stores ----
    float* sC = reinterpret_cast<float*>(smem);
#pragma unroll
    for (int mf = 0; mf < 2; mf++)
#pragma unroll
        for (int nf = 0; nf < 8; nf++) {
            int row = wm * 32 + mf * 16 + (lane >> 2);
            int col = wn * 64 + nf * 8 + (lane & 3) * 2;
            *reinterpret_cast<float2*>(&sC[row * 132 + col]) =
                make_float2(acc[mf][nf][0], acc[mf][nf][1]);
            *reinterpret_cast<float2*>(&sC[(row + 8) * 132 + col]) =
                make_float2(acc[mf][nf][2], acc[mf][nf][3]);
        }
    __syncthreads();
#pragma unroll
    for (int i = 0; i < 16; i++) {
        int j = t + i * 256;
        int row = j >> 5, seg = j & 31;
        float4 v = *reinterpret_cast<float4*>(&sC[row * 132 + seg * 4]);
        float bb = sBias[row];
        v.x += bb; v.y += bb; v.z += bb; v.w += bb;
        *reinterpret_cast<float4*>(
            Yg + ((size_t)b * MQ + m0 + row) * HWN + n0 + seg * 4) = v;
    }
}

// ---------------- 6) softmax(Q) + ctxT matvec + relu -> bf16 hi/lo planes ---------
__global__ __launch_bounds__(256) void attn_kernel()
{
    __shared__ float csT[DHEAD * DHEAD];
    int b = blockIdx.y;
    int t = threadIdx.y * 32 + threadIdx.x;
    for (int i = t; i < DHEAD * DHEAD; i += 256) {
        int d = i >> 5, e = i & 31;
        csT[e * DHEAD + d] = g_ctxT[b * 1024 + i];
    }
    __syncthreads();

    int n = blockIdx.x * 32 + threadIdx.x;
    int hh = threadIdx.y;
    const float* q = g_Q + ((size_t)b * MQ + hh * DHEAD) * HWN + n;

    float qv[DHEAD];
#pragma unroll
    for (int e = 0; e < DHEAD; e++) qv[e] = q[(size_t)e * HWN];

    float mx = -1e30f;
#pragma unroll
    for (int e = 0; e < DHEAD; e++) mx = fmaxf(mx, qv[e]);
    float s = 0.0f;
#pragma unroll
    for (int e = 0; e < DHEAD; e++) { qv[e] = __expf(qv[e] - mx); s += qv[e]; }
    float inv = 1.0f / s;
#pragma unroll
    for (int e = 0; e < DHEAD; e++) qv[e] *= inv;

    float att[DHEAD];
#pragma unroll
    for (int d = 0; d < DHEAD; d++) att[d] = 0.0f;
#pragma unroll
    for (int e = 0; e < DHEAD; e++) {
        float qe = qv[e];
        const float4* row = reinterpret_cast<const float4*>(&csT[e * DHEAD]);
#pragma unroll
        for (int j = 0; j < 8; j++) {
            float4 c4 = row[j];
            att[j * 4 + 0] += c4.x * qe;
            att[j * 4 + 1] += c4.y * qe;
            att[j * 4 + 2] += c4.z * qe;
            att[j * 4 + 3] += c4.w * qe;
        }
    }

    size_t base = ((size_t)b * MQ + hh * DHEAD) * HWN + n;
#pragma unroll
    for (int d = 0; d < DHEAD; d++) {
        float v = fmaxf(att[d], 0.0f);
        __nv_bfloat16 h = __float2bfloat16_rn(v);
        __nv_bfloat16 l = __float2bfloat16_rn(v - __bfloat162float(h));
        g_XH[base + (size_t)d * HWN] = h;
        g_XL[base + (size_t)d * HWN] = l;
    }
}

// ---------------- launch ------------------------------------------------------------
extern "C" void kernel_launch(void* const* d_in, const int* in_sizes, int n_in,
                              void* d_out, int out_size)
{
    const float* input = (const float*)d_in[0];
    const float* Wq  = (const float*)d_in[2];
    const float* gq  = (const float*)d_in[3];
    const float* bq  = (const float*)d_in[4];
    const float* mq  = (const float*)d_in[5];
    const float* vq  = (const float*)d_in[6];
    const float* Wkv = (const float*)d_in[7];
    const float* gkv = (const float*)d_in[8];
    const float* bkv = (const float*)d_in[9];
    const float* mkv = (const float*)d_in[10];
    const float* vkv = (const float*)d_in[11];
    const float* Wp  = (const float*)d_in[12];
    const float* gp  = (const float*)d_in[13];
    const float* bp  = (const float*)d_in[14];
    const float* mp  = (const float*)d_in[15];
    const float* vp  = (const float*)d_in[16];
    float* out = (float*)d_out;

    cudaFuncSetAttribute(mma_gemm_kernel, cudaFuncAttributeMaxDynamicSharedMemorySize,
                         GSMEM);

    fold_kernel<<<64, 256>>>(Wq, gq, bq, mq, vq,
                             Wkv, gkv, bkv, mkv, vkv,
                             Wp, gp, bp, mp, vp);
    kv_kernel<<<dim3(HWN / 256, BATCH), 256>>>(input);
    rowstats_kernel<<<dim3(DHEAD, BATCH), 256>>>();
    ctx_kernel<<<dim3(HWN / 128, BATCH), 256>>>();
    mma_gemm_kernel<<<dim3(HWN / 128, 2, BATCH), 256, GSMEM>>>(0, input, nullptr);
    attn_kernel<<<dim3(HWN / 32, BATCH), dim3(32, 8)>>>();
    mma_gemm_kernel<<<dim3(HWN / 128, 2, BATCH), 256, GSMEM>>>(1, nullptr, out);
}

// round 6
// speedup vs baseline: 2.0479x; 1.2353x over previous
#include <cuda_runtime.h>
#include <cuda_fp16.h>
#include <cstdint>

#define BATCH 16
#define CIN   256
#define HWN   4096
#define DHEAD 32
#define NHEAD 8
#define MQ    256

// ---------------- scratch (device globals) -----------------------------------
__device__ float g_KV[BATCH * DHEAD * HWN];
__device__ float g_ctxT[BATCH * DHEAD * DHEAD];
__device__ float g_rm[BATCH * DHEAD];
__device__ float g_rs[BATCH * DHEAD];
__device__ float g_Wkv[DHEAD * CIN]; __device__ float g_bkv[DHEAD];
__device__ float g_bq [MQ];          __device__ float g_bp [CIN];
// folded weights as fp16 hi/lo planes, [mode][m*256+k]
__device__ __half g_WH[2][MQ * CIN];
__device__ __half g_WL[2][MQ * CIN];
// relu(attended) as single fp16 plane, [b][k][n]
__device__ __half g_XF[(size_t)BATCH * MQ * HWN];

// ---------------- f32x2 helpers (kv kernel) -----------------------------------
#define PACKF2(u, lo, hi) asm("mov.b64 %0, {%1, %2};" : "=l"(u) : "f"(lo), "f"(hi))
#define UNPACKF2(lo, hi, u) asm("mov.b64 {%0, %1}, %2;" : "=f"(lo), "=f"(hi) : "l"(u))
#define FMAF2(c, a, b) asm("fma.rn.f32x2 %0, %1, %2, %0;" : "+l"(c) : "l"(a), "l"(b))

// ---------------- mma helpers ---------------------------------------------------
__device__ __forceinline__ void ldsm4(uint32_t* r, uint32_t addr) {
    asm volatile("ldmatrix.sync.aligned.m8n8.x4.shared.b16 {%0,%1,%2,%3}, [%4];\n"
        : "=r"(r[0]), "=r"(r[1]), "=r"(r[2]), "=r"(r[3]) : "r"(addr));
}
__device__ __forceinline__ void ldsm4t(uint32_t* r, uint32_t addr) {
    asm volatile("ldmatrix.sync.aligned.m8n8.x4.trans.shared.b16 {%0,%1,%2,%3}, [%4];\n"
        : "=r"(r[0]), "=r"(r[1]), "=r"(r[2]), "=r"(r[3]) : "r"(addr));
}
__device__ __forceinline__ void mma_f16(float* c, const uint32_t* a,
                                        uint32_t b0, uint32_t b1) {
    asm volatile(
        "mma.sync.aligned.m16n8k16.row.col.f32.f16.f16.f32 "
        "{%0,%1,%2,%3}, {%4,%5,%6,%7}, {%8,%9}, {%0,%1,%2,%3};\n"
        : "+f"(c[0]), "+f"(c[1]), "+f"(c[2]), "+f"(c[3])
        : "r"(a[0]), "r"(a[1]), "r"(a[2]), "r"(a[3]), "r"(b0), "r"(b1));
}
__device__ __forceinline__ uint32_t packh2(__half a, __half b) {
    return (uint32_t)__half_as_ushort(a) | ((uint32_t)__half_as_ushort(b) << 16);
}

// ---------------- 1) fold BN + fp16 hi/lo weight planes -----------------------
__global__ void fold_kernel(
    const float* __restrict__ Wq, const float* __restrict__ gq, const float* __restrict__ bq,
    const float* __restrict__ mq, const float* __restrict__ vq,
    const float* __restrict__ Wkv, const float* __restrict__ gkv, const float* __restrict__ bkv,
    const float* __restrict__ mkv, const float* __restrict__ vkv,
    const float* __restrict__ Wp, const float* __restrict__ gp, const float* __restrict__ bp,
    const float* __restrict__ mp, const float* __restrict__ vp)
{
    int t = blockIdx.x * blockDim.x + threadIdx.x;
    int stride = gridDim.x * blockDim.x;
    const float eps = 1e-5f;
    for (int i = t; i < MQ; i += stride) {
        float s = gq[i] * rsqrtf(vq[i] + eps); g_bq[i] = bq[i] - mq[i] * s;
    }
    for (int i = t; i < CIN; i += stride) {
        float s = gp[i] * rsqrtf(vp[i] + eps); g_bp[i] = bp[i] - mp[i] * s;
    }
    for (int i = t; i < DHEAD; i += stride) {
        float s = gkv[i] * rsqrtf(vkv[i] + eps); g_bkv[i] = bkv[i] - mkv[i] * s;
    }
    for (int i = t; i < DHEAD * CIN; i += stride) {
        int o = i / CIN; g_Wkv[i] = Wkv[i] * gkv[o] * rsqrtf(vkv[o] + eps);
    }
    for (int i = t; i < MQ * CIN; i += stride) {
        int m = i >> 8;
        {
            float s = gq[m] * rsqrtf(vq[m] + eps);
            float w = Wq[i] * s;
            __half h = __float2half_rn(w);
            g_WH[0][i] = h;
            g_WL[0][i] = __float2half_rn(w - __half2float(h));
        }
        {
            float s = gp[m] * rsqrtf(vp[m] + eps);
            float w = Wp[i] * s;
            __half h = __float2half_rn(w);
            g_WH[1][i] = h;
            g_WL[1][i] = __float2half_rn(w - __half2float(h));
        }
    }
}

// ---------------- 2) KV projection ----------------------------------------------
__global__ __launch_bounds__(256) void kv_kernel(const float* __restrict__ X)
{
    __shared__ __align__(16) float Ws[CIN][DHEAD];
    __shared__ float bs[DHEAD];
    int t = threadIdx.x;
    for (int i = t; i < DHEAD * CIN; i += 256) {
        int m = i / CIN, k = i % CIN;
        Ws[k][m] = g_Wkv[i];
    }
    if (t < DHEAD) bs[t] = g_bkv[t];
    __syncthreads();

    int b = blockIdx.y;
    int n = blockIdx.x * 256 + t;
    const float* x = X + (size_t)b * CIN * HWN + n;

    unsigned long long acc[16];
#pragma unroll
    for (int j = 0; j < 16; j++) PACKF2(acc[j], bs[2 * j], bs[2 * j + 1]);

#pragma unroll 4
    for (int k = 0; k < CIN; k++) {
        float xv = x[(size_t)k * HWN];
        unsigned long long xp; PACKF2(xp, xv, xv);
        const ulonglong2* wr = reinterpret_cast<const ulonglong2*>(&Ws[k][0]);
#pragma unroll
        for (int j = 0; j < 8; j++) {
            ulonglong2 w = wr[j];
            FMAF2(acc[2 * j],     w.x, xp);
            FMAF2(acc[2 * j + 1], w.y, xp);
        }
    }
    float* y = g_KV + (size_t)b * DHEAD * HWN + n;
#pragma unroll
    for (int j = 0; j < 16; j++) {
        float lo, hi; UNPACKF2(lo, hi, acc[j]);
        y[(size_t)(2 * j) * HWN] = lo;
        y[(size_t)(2 * j + 1) * HWN] = hi;
    }
}

// ---------------- 3) row softmax stats + zero ctxT -------------------------------
__global__ __launch_bounds__(256) void rowstats_kernel()
{
    __shared__ float red[8];
    int d = blockIdx.x, b = blockIdx.y, t = threadIdx.x;
    int w = t >> 5, l = t & 31;
    if (t < 32) g_ctxT[b * 1024 + d * 32 + t] = 0.0f;
    const float* row = g_KV + ((size_t)b * DHEAD + d) * HWN;

    float mx = -1e30f;
    for (int n = t; n < HWN; n += 256) mx = fmaxf(mx, row[n]);
#pragma unroll
    for (int o = 16; o > 0; o >>= 1) mx = fmaxf(mx, __shfl_xor_sync(~0u, mx, o));
    if (l == 0) red[w] = mx;
    __syncthreads();
    mx = red[0];
#pragma unroll
    for (int j = 1; j < 8; j++) mx = fmaxf(mx, red[j]);
    __syncthreads();

    float s = 0.0f;
    for (int n = t; n < HWN; n += 256) s += __expf(row[n] - mx);
#pragma unroll
    for (int o = 16; o > 0; o >>= 1) s += __shfl_xor_sync(~0u, s, o);
    if (l == 0) red[w] = s;
    __syncthreads();
    if (t == 0) {
        float tot = 0.0f;
#pragma unroll
        for (int j = 0; j < 8; j++) tot += red[j];
        g_rm[b * DHEAD + d] = mx;
        g_rs[b * DHEAD + d] = tot;
    }
}

// ---------------- 4) ctxT ----------------------------------------------------------
__global__ __launch_bounds__(256) void ctx_kernel()
{
    __shared__ float kvs[DHEAD][129];
    __shared__ float ps [DHEAD][129];
    __shared__ float ms[DHEAD], ssi[DHEAD];

    int b = blockIdx.y, t = threadIdx.x;
    if (t < DHEAD) { ms[t] = g_rm[b * DHEAD + t]; ssi[t] = 1.0f / g_rs[b * DHEAD + t]; }
    __syncthreads();

    int n0 = blockIdx.x * 128;
    for (int i = t; i < DHEAD * 128; i += 256) {
        int r = i >> 7, nn = i & 127;
        float v = g_KV[((size_t)b * DHEAD + r) * HWN + n0 + nn];
        kvs[r][nn] = v;
        ps [r][nn] = __expf(v - ms[r]) * ssi[r];
    }
    __syncthreads();

    int d = t & 31, e0 = (t >> 5) * 4;
    float acc[4] = {0.f, 0.f, 0.f, 0.f};
#pragma unroll 4
    for (int nn = 0; nn < 128; nn++) {
        float kd = kvs[d][nn];
#pragma unroll
        for (int j = 0; j < 4; j++) acc[j] += ps[e0 + j][nn] * kd;
    }
#pragma unroll
    for (int j = 0; j < 4; j++)
        atomicAdd(&g_ctxT[b * 1024 + d * 32 + (e0 + j)], acc[j]);
}

// ---------------- 5) qattn: GEMM0 (2-pass fp16) + softmax + ctxT-matvec + relu ----
// M tile = 256 (full), N tile = 128, 512 threads (16 warps: wm = wid>>1 owns head wm,
// wn = wid&1 owns 64-col half). X output: single fp16 plane g_XF.
// ctxT tiles use stride 40 halves (80 B, 16B multiple) for ldmatrix alignment.
#define QA_WH   0
#define QA_WL   36864
#define QA_XH   73728
#define QA_CSH  91136
#define QA_CSL  93696
#define QA_BIAS 96256
#define QA_Q    0         /* reuses W region after mainloop */
#define QA_SMEM 97280

__global__ void __launch_bounds__(512, 1) qattn_kernel(const float* __restrict__ Xf)
{
    extern __shared__ __align__(16) char smem[];
    __half* sWh = reinterpret_cast<__half*>(smem + QA_WH);
    __half* sWl = reinterpret_cast<__half*>(smem + QA_WL);
    __half* sXh = reinterpret_cast<__half*>(smem + QA_XH);
    __half* sCh = reinterpret_cast<__half*>(smem + QA_CSH);
    __half* sCl = reinterpret_cast<__half*>(smem + QA_CSL);
    float* sBias = reinterpret_cast<float*>(smem + QA_BIAS);
    __half* sQ  = reinterpret_cast<__half*>(smem + QA_Q);
    uint32_t sb = (uint32_t)__cvta_generic_to_shared(smem);

    int t = threadIdx.x, lane = t & 31, wid = t >> 5;
    int wm = wid >> 1, wn = wid & 1;
    int nt = blockIdx.x, b = blockIdx.y;
    int n0 = nt * 128;

    // preload ctxT (hi/lo fp16, stride 40) and bias
    for (int i = t; i < 1024; i += 512) {
        int d = i >> 5, e = i & 31;
        float f = g_ctxT[b * 1024 + i];
        __half h = __float2half_rn(f);
        sCh[d * 40 + e] = h;
        sCl[d * 40 + e] = __float2half_rn(f - __half2float(h));
    }
    if (t < 256) sBias[t] = g_bq[t];

    float acc[2][8][4];
#pragma unroll
    for (int i = 0; i < 2; i++)
#pragma unroll
        for (int j = 0; j < 8; j++)
#pragma unroll
            for (int k = 0; k < 4; k++) acc[i][j][k] = 0.0f;

    for (int c = 0; c < 4; c++) {
        int k0 = c * 64;
        // W tiles: 256 rows x 64 halves, stride 72
#pragma unroll
        for (int i = 0; i < 4; i++) {
            int j = t + i * 512;
            int row = j >> 3, seg = j & 7;
            size_t go = (size_t)row * CIN + k0 + seg * 8;
            *reinterpret_cast<uint4*>(sWh + row * 72 + seg * 8) =
                *reinterpret_cast<const uint4*>(g_WH[0] + go);
            *reinterpret_cast<uint4*>(sWl + row * 72 + seg * 8) =
                *reinterpret_cast<const uint4*>(g_WL[0] + go);
        }
        // X tile: 64 rows x 128 cols fp32 -> fp16, stride 136
#pragma unroll
        for (int i = 0; i < 4; i++) {
            int j = t + i * 512;
            int k = j >> 5, seg = j & 31;
            float4 v = *reinterpret_cast<const float4*>(
                Xf + ((size_t)b * CIN + k0 + k) * HWN + n0 + seg * 4);
            uint2 p;
            p.x = packh2(__float2half_rn(v.x), __float2half_rn(v.y));
            p.y = packh2(__float2half_rn(v.z), __float2half_rn(v.w));
            *reinterpret_cast<uint2*>(sXh + k * 136 + seg * 4) = p;
        }
        __syncthreads();

#pragma unroll
        for (int ks = 0; ks < 4; ks++) {
            int kk = ks * 16;
            uint32_t ah[2][4], al[2][4];
#pragma unroll
            for (int mf = 0; mf < 2; mf++) {
                int row = wm * 32 + mf * 16 + (lane & 15);
                int col = kk + (lane >> 4) * 8;
                uint32_t a_addr = sb + QA_WH + (uint32_t)(row * 72 + col) * 2;
                ldsm4(ah[mf], a_addr);
                ldsm4(al[mf], a_addr + (QA_WL - QA_WH));
            }
#pragma unroll
            for (int r = 0; r < 4; r++) {
                int kr = kk + (lane & 15);
                int coln = wn * 64 + r * 16 + (lane >> 4) * 8;
                uint32_t bh[4];
                ldsm4t(bh, sb + QA_XH + (uint32_t)(kr * 136 + coln) * 2);
#pragma unroll
                for (int mf = 0; mf < 2; mf++) {
                    mma_f16(acc[mf][r * 2],     ah[mf], bh[0], bh[1]);
                    mma_f16(acc[mf][r * 2 + 1], ah[mf], bh[2], bh[3]);
                    mma_f16(acc[mf][r * 2],     al[mf], bh[0], bh[1]);
                    mma_f16(acc[mf][r * 2 + 1], al[mf], bh[2], bh[3]);
                }
            }
        }
        __syncthreads();
    }

    // ---- fused epilogue: bias + per-column head softmax (head = wm) ----
    {
        int r0 = wm * 32 + (lane >> 2);
        float bv[4] = { sBias[r0], sBias[r0 + 8], sBias[r0 + 16], sBias[r0 + 24] };
#pragma unroll
        for (int mf = 0; mf < 2; mf++)
#pragma unroll
            for (int nf = 0; nf < 8; nf++)
#pragma unroll
                for (int k = 0; k < 4; k++)
                    acc[mf][nf][k] += bv[mf * 2 + (k >> 1)];
    }
#pragma unroll
    for (int nf = 0; nf < 8; nf++) {
#pragma unroll
        for (int p = 0; p < 2; p++) {
            float m = fmaxf(fmaxf(acc[0][nf][p], acc[0][nf][p + 2]),
                            fmaxf(acc[1][nf][p], acc[1][nf][p + 2]));
            m = fmaxf(m, __shfl_xor_sync(~0u, m, 4));
            m = fmaxf(m, __shfl_xor_sync(~0u, m, 8));
            m = fmaxf(m, __shfl_xor_sync(~0u, m, 16));
            float e00 = __expf(acc[0][nf][p] - m);
            float e01 = __expf(acc[0][nf][p + 2] - m);
            float e10 = __expf(acc[1][nf][p] - m);
            float e11 = __expf(acc[1][nf][p + 2] - m);
            float s = e00 + e01 + e10 + e11;
            s += __shfl_xor_sync(~0u, s, 4);
            s += __shfl_xor_sync(~0u, s, 8);
            s += __shfl_xor_sync(~0u, s, 16);
            float inv = 1.0f / s;
            acc[0][nf][p]     = e00 * inv;
            acc[0][nf][p + 2] = e01 * inv;
            acc[1][nf][p]     = e10 * inv;
            acc[1][nf][p + 2] = e11 * inv;
        }
    }
    // stage softmaxed q (fp16, stride 136) — warp-local block only
#pragma unroll
    for (int mf = 0; mf < 2; mf++)
#pragma unroll
        for (int nf = 0; nf < 8; nf++) {
            int row = wm * 32 + mf * 16 + (lane >> 2);
            int col = wn * 64 + nf * 8 + (lane & 3) * 2;
            *reinterpret_cast<uint32_t*>(sQ + row * 136 + col) =
                packh2(__float2half_rn(acc[mf][nf][0]), __float2half_rn(acc[mf][nf][1]));
            *reinterpret_cast<uint32_t*>(sQ + (row + 8) * 136 + col) =
                packh2(__float2half_rn(acc[mf][nf][2]), __float2half_rn(acc[mf][nf][3]));
        }
    __syncwarp();

    // att = ctxT @ q  (2-pass: Ch + Cl, q single)
    float att[2][8][4];
#pragma unroll
    for (int i = 0; i < 2; i++)
#pragma unroll
        for (int j = 0; j < 8; j++)
#pragma unroll
            for (int k = 0; k < 4; k++) att[i][j][k] = 0.0f;

#pragma unroll
    for (int kf = 0; kf < 2; kf++) {
        uint32_t ach[2][4], acl[2][4];
#pragma unroll
        for (int mf = 0; mf < 2; mf++) {
            int row = mf * 16 + (lane & 15);
            int col = kf * 16 + (lane >> 4) * 8;
            uint32_t a_addr = sb + QA_CSH + (uint32_t)(row * 40 + col) * 2;
            ldsm4(ach[mf], a_addr);
            ldsm4(acl[mf], a_addr + (QA_CSL - QA_CSH));
        }
#pragma unroll
        for (int r = 0; r < 4; r++) {
            int kr = wm * 32 + kf * 16 + (lane & 15);
            int coln = wn * 64 + r * 16 + (lane >> 4) * 8;
            uint32_t qb[4];
            ldsm4t(qb, sb + QA_Q + (uint32_t)(kr * 136 + coln) * 2);
#pragma unroll
            for (int mf = 0; mf < 2; mf++) {
                mma_f16(att[mf][r * 2],     ach[mf], qb[0], qb[1]);
                mma_f16(att[mf][r * 2 + 1], ach[mf], qb[2], qb[3]);
                mma_f16(att[mf][r * 2],     acl[mf], qb[0], qb[1]);
                mma_f16(att[mf][r * 2 + 1], acl[mf], qb[2], qb[3]);
            }
        }
    }

    // relu + fp16 store
#pragma unroll
    for (int mf = 0; mf < 2; mf++)
#pragma unroll
        for (int nf = 0; nf < 8; nf++) {
            int row = wm * 32 + mf * 16 + (lane >> 2);
            int col = n0 + wn * 64 + nf * 8 + (lane & 3) * 2;
            float v0 = fmaxf(att[mf][nf][0], 0.f), v1 = fmaxf(att[mf][nf][1], 0.f);
            float v2 = fmaxf(att[mf][nf][2], 0.f), v3 = fmaxf(att[mf][nf][3], 0.f);
            *reinterpret_cast<uint32_t*>(&g_XF[((size_t)(b * MQ) + row) * HWN + col]) =
                packh2(__float2half_rn(v0), __float2half_rn(v1));
            *reinterpret_cast<uint32_t*>(&g_XF[((size_t)(b * MQ) + row + 8) * HWN + col]) =
                packh2(__float2half_rn(v2), __float2half_rn(v3));
        }
}

// ---------------- 6) proj GEMM (2-pass fp16): out = Wp @ X + bias ------------------
#define G1_WH   0
#define G1_WL   36864
#define G1_XH   73728
#define G1_SMEM 91136

__global__ void __launch_bounds__(512, 1) proj_kernel(float* __restrict__ out)
{
    extern __shared__ __align__(16) char smem[];
    __half* sWh = reinterpret_cast<__half*>(smem + G1_WH);
    __half* sWl = reinterpret_cast<__half*>(smem + G1_WL);
    __half* sXh = reinterpret_cast<__half*>(smem + G1_XH);
    uint32_t sb = (uint32_t)__cvta_generic_to_shared(smem);

    int t = threadIdx.x, lane = t & 31, wid = t >> 5;
    int wm = wid >> 1, wn = wid & 1;
    int nt = blockIdx.x, b = blockIdx.y;
    int n0 = nt * 128;

    float acc[2][8][4];
#pragma unroll
    for (int i = 0; i < 2; i++)
#pragma unroll
        for (int j = 0; j < 8; j++)
#pragma unroll
            for (int k = 0; k < 4; k++) acc[i][j][k] = 0.0f;

    for (int c = 0; c < 4; c++) {
        int k0 = c * 64;
#pragma unroll
        for (int i = 0; i < 4; i++) {
            int j = t + i * 512;
            int row = j >> 3, seg = j & 7;
            size_t go = (size_t)row * CIN + k0 + seg * 8;
            *reinterpret_cast<uint4*>(sWh + row * 72 + seg * 8) =
                *reinterpret_cast<const uint4*>(g_WH[1] + go);
            *reinterpret_cast<uint4*>(sWl + row * 72 + seg * 8) =
                *reinterpret_cast<const uint4*>(g_WL[1] + go);
        }
#pragma unroll
        for (int i = 0; i < 2; i++) {
            int j = t + i * 512;
            int k = j >> 4, seg = j & 15;
            *reinterpret_cast<uint4*>(sXh + k * 136 + seg * 8) =
                *reinterpret_cast<const uint4*>(
                    g_XF + ((size_t)(b * MQ) + k0 + k) * HWN + n0 + seg * 8);
        }
        __syncthreads();

#pragma unroll
        for (int ks = 0; ks < 4; ks++) {
            int kk = ks * 16;
            uint32_t ah[2][4], al[2][4];
#pragma unroll
            for (int mf = 0; mf < 2; mf++) {
                int row = wm * 32 + mf * 16 + (lane & 15);
                int col = kk + (lane >> 4) * 8;
                uint32_t a_addr = sb + G1_WH + (uint32_t)(row * 72 + col) * 2;
                ldsm4(ah[mf], a_addr);
                ldsm4(al[mf], a_addr + (G1_WL - G1_WH));
            }
#pragma unroll
            for (int r = 0; r < 4; r++) {
                int kr = kk + (lane & 15);
                int coln = wn * 64 + r * 16 + (lane >> 4) * 8;
                uint32_t bh[4];
                ldsm4t(bh, sb + G1_XH + (uint32_t)(kr * 136 + coln) * 2);
#pragma unroll
                for (int mf = 0; mf < 2; mf++) {
                    mma_f16(acc[mf][r * 2],     ah[mf], bh[0], bh[1]);
                    mma_f16(acc[mf][r * 2 + 1], ah[mf], bh[2], bh[3]);
                    mma_f16(acc[mf][r * 2],     al[mf], bh[0], bh[1]);
                    mma_f16(acc[mf][r * 2 + 1], al[mf], bh[2], bh[3]);
                }
            }
        }
        __syncthreads();
    }

    int r0 = wm * 32 + (lane >> 2);
    float bv[4] = { g_bp[r0], g_bp[r0 + 8], g_bp[r0 + 16], g_bp[r0 + 24] };
#pragma unroll
    for (int mf = 0; mf < 2; mf++)
#pragma unroll
        for (int nf = 0; nf < 8; nf++) {
            int row = wm * 32 + mf * 16 + (lane >> 2);
            int col = n0 + wn * 64 + nf * 8 + (lane & 3) * 2;
            float bb0 = bv[mf * 2], bb1 = bv[mf * 2 + 1];
            *reinterpret_cast<float2*>(&out[((size_t)(b * MQ) + row) * HWN + col]) =
                make_float2(acc[mf][nf][0] + bb0, acc[mf][nf][1] + bb0);
            *reinterpret_cast<float2*>(&out[((size_t)(b * MQ) + row + 8) * HWN + col]) =
                make_float2(acc[mf][nf][2] + bb1, acc[mf][nf][3] + bb1);
        }
}

// ---------------- launch ------------------------------------------------------------
extern "C" void kernel_launch(void* const* d_in, const int* in_sizes, int n_in,
                              void* d_out, int out_size)
{
    const float* input = (const float*)d_in[0];
    const float* Wq  = (const float*)d_in[2];
    const float* gq  = (const float*)d_in[3];
    const float* bq  = (const float*)d_in[4];
    const float* mq  = (const float*)d_in[5];
    const float* vq  = (const float*)d_in[6];
    const float* Wkv = (const float*)d_in[7];
    const float* gkv = (const float*)d_in[8];
    const float* bkv = (const float*)d_in[9];
    const float* mkv = (const float*)d_in[10];
    const float* vkv = (const float*)d_in[11];
    const float* Wp  = (const float*)d_in[12];
    const float* gp  = (const float*)d_in[13];
    const float* bp  = (const float*)d_in[14];
    const float* mp  = (const float*)d_in[15];
    const float* vp  = (const float*)d_in[16];
    float* out = (float*)d_out;

    cudaFuncSetAttribute(qattn_kernel, cudaFuncAttributeMaxDynamicSharedMemorySize, QA_SMEM);
    cudaFuncSetAttribute(proj_kernel, cudaFuncAttributeMaxDynamicSharedMemorySize, G1_SMEM);

    fold_kernel<<<64, 256>>>(Wq, gq, bq, mq, vq,
                             Wkv, gkv, bkv, mkv, vkv,
                             Wp, gp, bp, mp, vp);
    kv_kernel<<<dim3(HWN / 256, BATCH), 256>>>(input);
    rowstats_kernel<<<dim3(DHEAD, BATCH), 256>>>();
    ctx_kernel<<<dim3(HWN / 128, BATCH), 256>>>();
    qattn_kernel<<<dim3(HWN / 128, BATCH), 512, QA_SMEM>>>(input);
    proj_kernel<<<dim3(HWN / 128, BATCH), 512, G1_SMEM>>>(out);
}

// round 7
// speedup vs baseline: 2.5588x; 1.2495x over previous
#include <cuda_runtime.h>
#include <cuda_fp16.h>
#include <cstdint>

#define BATCH 16
#define CIN   256
#define HWN   4096
#define DHEAD 32
#define NHEAD 8
#define MQ    256

// ---------------- scratch (device globals) -----------------------------------
__device__ float g_KV[BATCH * DHEAD * HWN];
__device__ float g_ctxT[BATCH * DHEAD * DHEAD];
__device__ float g_rm[BATCH * DHEAD];
__device__ float g_rs[BATCH * DHEAD];
__device__ float g_Wkv[DHEAD * CIN]; __device__ float g_bkv[DHEAD];
__device__ float g_bq [MQ];          __device__ float g_bp [CIN];
// folded weights as single fp16 plane, [mode][m*256+k]
__device__ __half g_WH[2][MQ * CIN];
// relu(attended) as single fp16 plane, [b][k][n]
__device__ __half g_XF[(size_t)BATCH * MQ * HWN];

// ---------------- f32x2 helpers (kv kernel) -----------------------------------
#define PACKF2(u, lo, hi) asm("mov.b64 %0, {%1, %2};" : "=l"(u) : "f"(lo), "f"(hi))
#define UNPACKF2(lo, hi, u) asm("mov.b64 {%0, %1}, %2;" : "=f"(lo), "=f"(hi) : "l"(u))
#define FMAF2(c, a, b) asm("fma.rn.f32x2 %0, %1, %2, %0;" : "+l"(c) : "l"(a), "l"(b))

// ---------------- mma / async helpers -------------------------------------------
__device__ __forceinline__ void ldsm4(uint32_t* r, uint32_t addr) {
    asm volatile("ldmatrix.sync.aligned.m8n8.x4.shared.b16 {%0,%1,%2,%3}, [%4];\n"
        : "=r"(r[0]), "=r"(r[1]), "=r"(r[2]), "=r"(r[3]) : "r"(addr));
}
__device__ __forceinline__ void ldsm4t(uint32_t* r, uint32_t addr) {
    asm volatile("ldmatrix.sync.aligned.m8n8.x4.trans.shared.b16 {%0,%1,%2,%3}, [%4];\n"
        : "=r"(r[0]), "=r"(r[1]), "=r"(r[2]), "=r"(r[3]) : "r"(addr));
}
__device__ __forceinline__ void mma_f16(float* c, const uint32_t* a,
                                        uint32_t b0, uint32_t b1) {
    asm volatile(
        "mma.sync.aligned.m16n8k16.row.col.f32.f16.f16.f32 "
        "{%0,%1,%2,%3}, {%4,%5,%6,%7}, {%8,%9}, {%0,%1,%2,%3};\n"
        : "+f"(c[0]), "+f"(c[1]), "+f"(c[2]), "+f"(c[3])
        : "r"(a[0]), "r"(a[1]), "r"(a[2]), "r"(a[3]), "r"(b0), "r"(b1));
}
__device__ __forceinline__ uint32_t packh2(__half a, __half b) {
    return (uint32_t)__half_as_ushort(a) | ((uint32_t)__half_as_ushort(b) << 16);
}
__device__ __forceinline__ void cp16(uint32_t saddr, const void* gptr) {
    asm volatile("cp.async.cg.shared.global [%0], [%1], 16;" :: "r"(saddr), "l"(gptr));
}
#define CP_COMMIT() asm volatile("cp.async.commit_group;" ::: "memory")
#define CP_WAIT0()  asm volatile("cp.async.wait_group 0;" ::: "memory")

// ---------------- 1) fold BN + fp16 weight plane -------------------------------
__global__ void fold_kernel(
    const float* __restrict__ Wq, const float* __restrict__ gq, const float* __restrict__ bq,
    const float* __restrict__ mq, const float* __restrict__ vq,
    const float* __restrict__ Wkv, const float* __restrict__ gkv, const float* __restrict__ bkv,
    const float* __restrict__ mkv, const float* __restrict__ vkv,
    const float* __restrict__ Wp, const float* __restrict__ gp, const float* __restrict__ bp,
    const float* __restrict__ mp, const float* __restrict__ vp)
{
    int t = blockIdx.x * blockDim.x + threadIdx.x;
    int stride = gridDim.x * blockDim.x;
    const float eps = 1e-5f;
    for (int i = t; i < MQ; i += stride) {
        float s = gq[i] * rsqrtf(vq[i] + eps); g_bq[i] = bq[i] - mq[i] * s;
    }
    for (int i = t; i < CIN; i += stride) {
        float s = gp[i] * rsqrtf(vp[i] + eps); g_bp[i] = bp[i] - mp[i] * s;
    }
    for (int i = t; i < DHEAD; i += stride) {
        float s = gkv[i] * rsqrtf(vkv[i] + eps); g_bkv[i] = bkv[i] - mkv[i] * s;
    }
    for (int i = t; i < DHEAD * CIN; i += stride) {
        int o = i / CIN; g_Wkv[i] = Wkv[i] * gkv[o] * rsqrtf(vkv[o] + eps);
    }
    for (int i = t; i < MQ * CIN; i += stride) {
        int m = i >> 8;
        g_WH[0][i] = __float2half_rn(Wq[i] * gq[m] * rsqrtf(vq[m] + eps));
        g_WH[1][i] = __float2half_rn(Wp[i] * gp[m] * rsqrtf(vp[m] + eps));
    }
}

// ---------------- 2) KV projection ----------------------------------------------
__global__ __launch_bounds__(256) void kv_kernel(const float* __restrict__ X)
{
    __shared__ __align__(16) float Ws[CIN][DHEAD];
    __shared__ float bs[DHEAD];
    int t = threadIdx.x;
    for (int i = t; i < DHEAD * CIN; i += 256) {
        int m = i / CIN, k = i % CIN;
        Ws[k][m] = g_Wkv[i];
    }
    if (t < DHEAD) bs[t] = g_bkv[t];
    __syncthreads();

    int b = blockIdx.y;
    int n = blockIdx.x * 256 + t;
    const float* x = X + (size_t)b * CIN * HWN + n;

    unsigned long long acc[16];
#pragma unroll
    for (int j = 0; j < 16; j++) PACKF2(acc[j], bs[2 * j], bs[2 * j + 1]);

#pragma unroll 4
    for (int k = 0; k < CIN; k++) {
        float xv = x[(size_t)k * HWN];
        unsigned long long xp; PACKF2(xp, xv, xv);
        const ulonglong2* wr = reinterpret_cast<const ulonglong2*>(&Ws[k][0]);
#pragma unroll
        for (int j = 0; j < 8; j++) {
            ulonglong2 w = wr[j];
            FMAF2(acc[2 * j],     w.x, xp);
            FMAF2(acc[2 * j + 1], w.y, xp);
        }
    }
    float* y = g_KV + (size_t)b * DHEAD * HWN + n;
#pragma unroll
    for (int j = 0; j < 16; j++) {
        float lo, hi; UNPACKF2(lo, hi, acc[j]);
        y[(size_t)(2 * j) * HWN] = lo;
        y[(size_t)(2 * j + 1) * HWN] = hi;
    }
}

// ---------------- 3) row softmax stats + zero ctxT -------------------------------
__global__ __launch_bounds__(256) void rowstats_kernel()
{
    __shared__ float red[8];
    int d = blockIdx.x, b = blockIdx.y, t = threadIdx.x;
    int w = t >> 5, l = t & 31;
    if (t < 32) g_ctxT[b * 1024 + d * 32 + t] = 0.0f;
    const float* row = g_KV + ((size_t)b * DHEAD + d) * HWN;

    float mx = -1e30f;
    for (int n = t; n < HWN; n += 256) mx = fmaxf(mx, row[n]);
#pragma unroll
    for (int o = 16; o > 0; o >>= 1) mx = fmaxf(mx, __shfl_xor_sync(~0u, mx, o));
    if (l == 0) red[w] = mx;
    __syncthreads();
    mx = red[0];
#pragma unroll
    for (int j = 1; j < 8; j++) mx = fmaxf(mx, red[j]);
    __syncthreads();

    float s = 0.0f;
    for (int n = t; n < HWN; n += 256) s += __expf(row[n] - mx);
#pragma unroll
    for (int o = 16; o > 0; o >>= 1) s += __shfl_xor_sync(~0u, s, o);
    if (l == 0) red[w] = s;
    __syncthreads();
    if (t == 0) {
        float tot = 0.0f;
#pragma unroll
        for (int j = 0; j < 8; j++) tot += red[j];
        g_rm[b * DHEAD + d] = mx;
        g_rs[b * DHEAD + d] = tot;
    }
}

// ---------------- 4) ctxT ----------------------------------------------------------
__global__ __launch_bounds__(256) void ctx_kernel()
{
    __shared__ float kvs[DHEAD][129];
    __shared__ float ps [DHEAD][129];
    __shared__ float ms[DHEAD], ssi[DHEAD];

    int b = blockIdx.y, t = threadIdx.x;
    if (t < DHEAD) { ms[t] = g_rm[b * DHEAD + t]; ssi[t] = 1.0f / g_rs[b * DHEAD + t]; }
    __syncthreads();

    int n0 = blockIdx.x * 128;
    for (int i = t; i < DHEAD * 128; i += 256) {
        int r = i >> 7, nn = i & 127;
        float v = g_KV[((size_t)b * DHEAD + r) * HWN + n0 + nn];
        kvs[r][nn] = v;
        ps [r][nn] = __expf(v - ms[r]) * ssi[r];
    }
    __syncthreads();

    int d = t & 31, e0 = (t >> 5) * 4;
    float acc[4] = {0.f, 0.f, 0.f, 0.f};
#pragma unroll 4
    for (int nn = 0; nn < 128; nn++) {
        float kd = kvs[d][nn];
#pragma unroll
        for (int j = 0; j < 4; j++) acc[j] += ps[e0 + j][nn] * kd;
    }
#pragma unroll
    for (int j = 0; j < 4; j++)
        atomicAdd(&g_ctxT[b * 1024 + d * 32 + (e0 + j)], acc[j]);
}

// ---------------- 5) qattn: pipelined GEMM0 + softmax + ctxT-matvec + relu --------
// M=256 full, N=128 per CTA, 512 threads. Single fp16 W pass, 2-stage double buffer:
// W via cp.async, X via register prefetch + fp16 convert.
#define QA_WS0  0
#define QA_WS1  36864
#define QA_XS0  73728
#define QA_XS1  91136
#define QA_CSH  108544
#define QA_CSL  111104
#define QA_BIAS 113664
#define QA_SMEM 114688
#define QA_Q    0          /* sQ (69632 B) reuses W stages after mainloop */

__global__ void __launch_bounds__(512, 1) qattn_kernel(const float* __restrict__ Xf)
{
    extern __shared__ __align__(16) char smem[];
    __half* sCh = reinterpret_cast<__half*>(smem + QA_CSH);
    __half* sCl = reinterpret_cast<__half*>(smem + QA_CSL);
    float* sBias = reinterpret_cast<float*>(smem + QA_BIAS);
    __half* sQ  = reinterpret_cast<__half*>(smem + QA_Q);
    uint32_t sb = (uint32_t)__cvta_generic_to_shared(smem);

    int t = threadIdx.x, lane = t & 31, wid = t >> 5;
    int wm = wid >> 1, wn = wid & 1;
    int nt = blockIdx.x, b = blockIdx.y;
    int n0 = nt * 128;
    const __half* W = g_WH[0];

    // preload ctxT (hi/lo fp16, stride 40) and bias
    for (int i = t; i < 1024; i += 512) {
        int d = i >> 5, e = i & 31;
        float f = g_ctxT[b * 1024 + i];
        __half h = __float2half_rn(f);
        sCh[d * 40 + e] = h;
        sCl[d * 40 + e] = __float2half_rn(f - __half2float(h));
    }
    if (t < 256) sBias[t] = g_bq[t];

    // ---- prologue: chunk 0 ----
#pragma unroll
    for (int i = 0; i < 4; i++) {
        int j = t + i * 512;
        int row = j >> 3, seg = j & 7;
        cp16(sb + QA_WS0 + (uint32_t)(row * 72 + seg * 8) * 2,
             W + (size_t)row * CIN + seg * 8);
    }
    CP_COMMIT();
    float4 xr[4];
#pragma unroll
    for (int i = 0; i < 4; i++) {
        int j = t + i * 512;
        int k = j >> 5, seg = j & 31;
        xr[i] = *reinterpret_cast<const float4*>(
            Xf + ((size_t)b * CIN + k) * HWN + n0 + seg * 4);
    }
    CP_WAIT0();
#pragma unroll
    for (int i = 0; i < 4; i++) {
        int j = t + i * 512;
        int k = j >> 5, seg = j & 31;
        uint2 p;
        p.x = packh2(__float2half_rn(xr[i].x), __float2half_rn(xr[i].y));
        p.y = packh2(__float2half_rn(xr[i].z), __float2half_rn(xr[i].w));
        *reinterpret_cast<uint2*>(smem + QA_XS0 + (k * 136 + seg * 4) * 2) = p;
    }
    __syncthreads();

    float acc[2][8][4];
#pragma unroll
    for (int i = 0; i < 2; i++)
#pragma unroll
        for (int j = 0; j < 8; j++)
#pragma unroll
            for (int k = 0; k < 4; k++) acc[i][j][k] = 0.0f;

    for (int c = 0; c < 4; c++) {
        int s = c & 1;
        uint32_t wbase = sb + (s ? QA_WS1 : QA_WS0);
        uint32_t xbase = sb + (s ? QA_XS1 : QA_XS0);
        if (c < 3) {
            int k0n = (c + 1) * 64;
            uint32_t wdst = sb + (s ? QA_WS0 : QA_WS1);
#pragma unroll
            for (int i = 0; i < 4; i++) {
                int j = t + i * 512;
                int row = j >> 3, seg = j & 7;
                cp16(wdst + (uint32_t)(row * 72 + seg * 8) * 2,
                     W + (size_t)row * CIN + k0n + seg * 8);
            }
            CP_COMMIT();
#pragma unroll
            for (int i = 0; i < 4; i++) {
                int j = t + i * 512;
                int k = j >> 5, seg = j & 31;
                xr[i] = *reinterpret_cast<const float4*>(
                    Xf + ((size_t)b * CIN + k0n + k) * HWN + n0 + seg * 4);
            }
        }
        // compute chunk c
#pragma unroll
        for (int ks = 0; ks < 4; ks++) {
            int kk = ks * 16;
            uint32_t ah[2][4];
#pragma unroll
            for (int mf = 0; mf < 2; mf++) {
                int row = wm * 32 + mf * 16 + (lane & 15);
                int col = kk + (lane >> 4) * 8;
                ldsm4(ah[mf], wbase + (uint32_t)(row * 72 + col) * 2);
            }
#pragma unroll
            for (int r = 0; r < 4; r++) {
                int kr = kk + (lane & 15);
                int coln = wn * 64 + r * 16 + (lane >> 4) * 8;
                uint32_t bh[4];
                ldsm4t(bh, xbase + (uint32_t)(kr * 136 + coln) * 2);
#pragma unroll
                for (int mf = 0; mf < 2; mf++) {
                    mma_f16(acc[mf][r * 2],     ah[mf], bh[0], bh[1]);
                    mma_f16(acc[mf][r * 2 + 1], ah[mf], bh[2], bh[3]);
                }
            }
        }
        if (c < 3) {
            CP_WAIT0();
            char* xdst = smem + (s ? QA_XS0 : QA_XS1);
#pragma unroll
            for (int i = 0; i < 4; i++) {
                int j = t + i * 512;
                int k = j >> 5, seg = j & 31;
                uint2 p;
                p.x = packh2(__float2half_rn(xr[i].x), __float2half_rn(xr[i].y));
                p.y = packh2(__float2half_rn(xr[i].z), __float2half_rn(xr[i].w));
                *reinterpret_cast<uint2*>(xdst + (k * 136 + seg * 4) * 2) = p;
            }
            __syncthreads();
        }
    }
    __syncthreads();   // all compute done before sQ overwrites W stages

    // ---- fused epilogue: bias + per-column head softmax (head = wm) ----
    {
        int r0 = wm * 32 + (lane >> 2);
        float bv[4] = { sBias[r0], sBias[r0 + 8], sBias[r0 + 16], sBias[r0 + 24] };
#pragma unroll
        for (int mf = 0; mf < 2; mf++)
#pragma unroll
            for (int nf = 0; nf < 8; nf++)
#pragma unroll
                for (int k = 0; k < 4; k++)
                    acc[mf][nf][k] += bv[mf * 2 + (k >> 1)];
    }
#pragma unroll
    for (int nf = 0; nf < 8; nf++) {
#pragma unroll
        for (int p = 0; p < 2; p++) {
            float m = fmaxf(fmaxf(acc[0][nf][p], acc[0][nf][p + 2]),
                            fmaxf(acc[1][nf][p], acc[1][nf][p + 2]));
            m = fmaxf(m, __shfl_xor_sync(~0u, m, 4));
            m = fmaxf(m, __shfl_xor_sync(~0u, m, 8));
            m = fmaxf(m, __shfl_xor_sync(~0u, m, 16));
            float e00 = __expf(acc[0][nf][p] - m);
            float e01 = __expf(acc[0][nf][p + 2] - m);
            float e10 = __expf(acc[1][nf][p] - m);
            float e11 = __expf(acc[1][nf][p + 2] - m);
            float s = e00 + e01 + e10 + e11;
            s += __shfl_xor_sync(~0u, s, 4);
            s += __shfl_xor_sync(~0u, s, 8);
            s += __shfl_xor_sync(~0u, s, 16);
            float inv = 1.0f / s;
            acc[0][nf][p]     = e00 * inv;
            acc[0][nf][p + 2] = e01 * inv;
            acc[1][nf][p]     = e10 * inv;
            acc[1][nf][p + 2] = e11 * inv;
        }
    }
    // stage softmaxed q (fp16, stride 136) — warp-local block only
#pragma unroll
    for (int mf = 0; mf < 2; mf++)
#pragma unroll
        for (int nf = 0; nf < 8; nf++) {
            int row = wm * 32 + mf * 16 + (lane >> 2);
            int col = wn * 64 + nf * 8 + (lane & 3) * 2;
            *reinterpret_cast<uint32_t*>(sQ + row * 136 + col) =
                packh2(__float2half_rn(acc[mf][nf][0]), __float2half_rn(acc[mf][nf][1]));
            *reinterpret_cast<uint32_t*>(sQ + (row + 8) * 136 + col) =
                packh2(__float2half_rn(acc[mf][nf][2]), __float2half_rn(acc[mf][nf][3]));
        }
    __syncwarp();

    // att = ctxT @ q  (ctxT hi/lo 2-pass, q single)
    float att[2][8][4];
#pragma unroll
    for (int i = 0; i < 2; i++)
#pragma unroll
        for (int j = 0; j < 8; j++)
#pragma unroll
            for (int k = 0; k < 4; k++) att[i][j][k] = 0.0f;

#pragma unroll
    for (int kf = 0; kf < 2; kf++) {
        uint32_t ach[2][4], acl[2][4];
#pragma unroll
        for (int mf = 0; mf < 2; mf++) {
            int row = mf * 16 + (lane & 15);
            int col = kf * 16 + (lane >> 4) * 8;
            uint32_t a_addr = sb + QA_CSH + (uint32_t)(row * 40 + col) * 2;
            ldsm4(ach[mf], a_addr);
            ldsm4(acl[mf], a_addr + (QA_CSL - QA_CSH));
        }
#pragma unroll
        for (int r = 0; r < 4; r++) {
            int kr = wm * 32 + kf * 16 + (lane & 15);
            int coln = wn * 64 + r * 16 + (lane >> 4) * 8;
            uint32_t qb[4];
            ldsm4t(qb, sb + QA_Q + (uint32_t)(kr * 136 + coln) * 2);
#pragma unroll
            for (int mf = 0; mf < 2; mf++) {
                mma_f16(att[mf][r * 2],     ach[mf], qb[0], qb[1]);
                mma_f16(att[mf][r * 2 + 1], ach[mf], qb[2], qb[3]);
                mma_f16(att[mf][r * 2],     acl[mf], qb[0], qb[1]);
                mma_f16(att[mf][r * 2 + 1], acl[mf], qb[2], qb[3]);
            }
        }
    }

    // relu + fp16 store
#pragma unroll
    for (int mf = 0; mf < 2; mf++)
#pragma unroll
        for (int nf = 0; nf < 8; nf++) {
            int row = wm * 32 + mf * 16 + (lane >> 2);
            int col = n0 + wn * 64 + nf * 8 + (lane & 3) * 2;
            float v0 = fmaxf(att[mf][nf][0], 0.f), v1 = fmaxf(att[mf][nf][1], 0.f);
            float v2 = fmaxf(att[mf][nf][2], 0.f), v3 = fmaxf(att[mf][nf][3], 0.f);
            *reinterpret_cast<uint32_t*>(&g_XF[((size_t)(b * MQ) + row) * HWN + col]) =
                packh2(__float2half_rn(v0), __float2half_rn(v1));
            *reinterpret_cast<uint32_t*>(&g_XF[((size_t)(b * MQ) + row + 8) * HWN + col]) =
                packh2(__float2half_rn(v2), __float2half_rn(v3));
        }
}

// ---------------- 6) proj: pipelined single-pass fp16 GEMM ------------------------
#define G1_WS0  0
#define G1_WS1  36864
#define G1_XS0  73728
#define G1_XS1  91136
#define G1_SMEM 108544

__global__ void __launch_bounds__(512, 1) proj_kernel(float* __restrict__ out)
{
    extern __shared__ __align__(16) char smem[];
    uint32_t sb = (uint32_t)__cvta_generic_to_shared(smem);

    int t = threadIdx.x, lane = t & 31, wid = t >> 5;
    int wm = wid >> 1, wn = wid & 1;
    int nt = blockIdx.x, b = blockIdx.y;
    int n0 = nt * 128;
    const __half* W = g_WH[1];

    // prologue: chunk 0
#pragma unroll
    for (int i = 0; i < 4; i++) {
        int j = t + i * 512;
        int row = j >> 3, seg = j & 7;
        cp16(sb + G1_WS0 + (uint32_t)(row * 72 + seg * 8) * 2,
             W + (size_t)row * CIN + seg * 8);
    }
#pragma unroll
    for (int i = 0; i < 2; i++) {
        int j = t + i * 512;
        int k = j >> 4, seg = j & 15;
        cp16(sb + G1_XS0 + (uint32_t)(k * 136 + seg * 8) * 2,
             g_XF + ((size_t)(b * MQ) + k) * HWN + n0 + seg * 8);
    }
    CP_COMMIT();
    CP_WAIT0();
    __syncthreads();

    float acc[2][8][4];
#pragma unroll
    for (int i = 0; i < 2; i++)
#pragma unroll
        for (int j = 0; j < 8; j++)
#pragma unroll
            for (int k = 0; k < 4; k++) acc[i][j][k] = 0.0f;

    for (int c = 0; c < 4; c++) {
        int s = c & 1;
        uint32_t wbase = sb + (s ? G1_WS1 : G1_WS0);
        uint32_t xbase = sb + (s ? G1_XS1 : G1_XS0);
        if (c < 3) {
            int k0n = (c + 1) * 64;
            uint32_t wdst = sb + (s ? G1_WS0 : G1_WS1);
            uint32_t xdst = sb + (s ? G1_XS0 : G1_XS1);
#pragma unroll
            for (int i = 0; i < 4; i++) {
                int j = t + i * 512;
                int row = j >> 3, seg = j & 7;
                cp16(wdst + (uint32_t)(row * 72 + seg * 8) * 2,
                     W + (size_t)row * CIN + k0n + seg * 8);
            }
#pragma unroll
            for (int i = 0; i < 2; i++) {
                int j = t + i * 512;
                int k = j >> 4, seg = j & 15;
                cp16(xdst + (uint32_t)(k * 136 + seg * 8) * 2,
                     g_XF + ((size_t)(b * MQ) + k0n + k) * HWN + n0 + seg * 8);
            }
            CP_COMMIT();
        }
#pragma unroll
        for (int ks = 0; ks < 4; ks++) {
            int kk = ks * 16;
            uint32_t ah[2][4];
#pragma unroll
            for (int mf = 0; mf < 2; mf++) {
                int row = wm * 32 + mf * 16 + (lane & 15);
                int col = kk + (lane >> 4) * 8;
                ldsm4(ah[mf], wbase + (uint32_t)(row * 72 + col) * 2);
            }
#pragma unroll
            for (int r = 0; r < 4; r++) {
                int kr = kk + (lane & 15);
                int coln = wn * 64 + r * 16 + (lane >> 4) * 8;
                uint32_t bh[4];
                ldsm4t(bh, xbase + (uint32_t)(kr * 136 + coln) * 2);
#pragma unroll
                for (int mf = 0; mf < 2; mf++) {
                    mma_f16(acc[mf][r * 2],     ah[mf], bh[0], bh[1]);
                    mma_f16(acc[mf][r * 2 + 1], ah[mf], bh[2], bh[3]);
                }
            }
        }
        if (c < 3) {
            CP_WAIT0();
            __syncthreads();
        }
    }

    int r0 = wm * 32 + (lane >> 2);
    float bv[4] = { g_bp[r0], g_bp[r0 + 8], g_bp[r0 + 16], g_bp[r0 + 24] };
#pragma unroll
    for (int mf = 0; mf < 2; mf++)
#pragma unroll
        for (int nf = 0; nf < 8; nf++) {
            int row = wm * 32 + mf * 16 + (lane >> 2);
            int col = n0 + wn * 64 + nf * 8 + (lane & 3) * 2;
            float bb0 = bv[mf * 2], bb1 = bv[mf * 2 + 1];
            *reinterpret_cast<float2*>(&out[((size_t)(b * MQ) + row) * HWN + col]) =
                make_float2(acc[mf][nf][0] + bb0, acc[mf][nf][1] + bb0);
            *reinterpret_cast<float2*>(&out[((size_t)(b * MQ) + row + 8) * HWN + col]) =
                make_float2(acc[mf][nf][2] + bb1, acc[mf][nf][3] + bb1);
        }
}

// ---------------- launch ------------------------------------------------------------
extern "C" void kernel_launch(void* const* d_in, const int* in_sizes, int n_in,
                              void* d_out, int out_size)
{
    const float* input = (const float*)d_in[0];
    const float* Wq  = (const float*)d_in[2];
    const float* gq  = (const float*)d_in[3];
    const float* bq  = (const float*)d_in[4];
    const float* mq  = (const float*)d_in[5];
    const float* vq  = (const float*)d_in[6];
    const float* Wkv = (const float*)d_in[7];
    const float* gkv = (const float*)d_in[8];
    const float* bkv = (const float*)d_in[9];
    const float* mkv = (const float*)d_in[10];
    const float* vkv = (const float*)d_in[11];
    const float* Wp  = (const float*)d_in[12];
    const float* gp  = (const float*)d_in[13];
    const float* bp  = (const float*)d_in[14];
    const float* mp  = (const float*)d_in[15];
    const float* vp  = (const float*)d_in[16];
    float* out = (float*)d_out;

    cudaFuncSetAttribute(qattn_kernel, cudaFuncAttributeMaxDynamicSharedMemorySize, QA_SMEM);
    cudaFuncSetAttribute(proj_kernel, cudaFuncAttributeMaxDynamicSharedMemorySize, G1_SMEM);

    fold_kernel<<<64, 256>>>(Wq, gq, bq, mq, vq,
                             Wkv, gkv, bkv, mkv, vkv,
                             Wp, gp, bp, mp, vp);
    kv_kernel<<<dim3(HWN / 256, BATCH), 256>>>(input);
    rowstats_kernel<<<dim3(DHEAD, BATCH), 256>>>();
    ctx_kernel<<<dim3(HWN / 128, BATCH), 256>>>();
    qattn_kernel<<<dim3(HWN / 128, BATCH), 512, QA_SMEM>>>(input);
    proj_kernel<<<dim3(HWN / 128, BATCH), 512, G1_SMEM>>>(out);
}

// round 8
// speedup vs baseline: 2.7118x; 1.0598x over previous
#include <cuda_runtime.h>
#include <cuda_fp16.h>
#include <cstdint>

#define BATCH 16
#define CIN   256
#define HWN   4096
#define DHEAD 32
#define NHEAD 8
#define MQ    256

// ---------------- scratch (device globals) -----------------------------------
__device__ float g_KV[BATCH * DHEAD * HWN];
__device__ float g_ctxT[BATCH * DHEAD * DHEAD];
__device__ float g_rm[BATCH * DHEAD];
__device__ float g_rs[BATCH * DHEAD];
__device__ float g_Wkv[DHEAD * CIN]; __device__ float g_bkv[DHEAD];
__device__ float g_bq [MQ];          __device__ float g_bp [CIN];
// folded weights as single fp16 plane, [mode][m*256+k]
__device__ __half g_WH[2][MQ * CIN];
// fp16 copy of the input, [b][k][n]  (written by kv_kernel)
__device__ __half g_XIN[(size_t)BATCH * CIN * HWN];
// relu(attended) as single fp16 plane, [b][k][n]
__device__ __half g_XF[(size_t)BATCH * MQ * HWN];

// ---------------- f32x2 helpers (kv kernel) -----------------------------------
#define PACKF2(u, lo, hi) asm("mov.b64 %0, {%1, %2};" : "=l"(u) : "f"(lo), "f"(hi))
#define UNPACKF2(lo, hi, u) asm("mov.b64 {%0, %1}, %2;" : "=f"(lo), "=f"(hi) : "l"(u))
#define FMAF2(c, a, b) asm("fma.rn.f32x2 %0, %1, %2, %0;" : "+l"(c) : "l"(a), "l"(b))

// ---------------- mma / async helpers -------------------------------------------
__device__ __forceinline__ void ldsm4(uint32_t* r, uint32_t addr) {
    asm volatile("ldmatrix.sync.aligned.m8n8.x4.shared.b16 {%0,%1,%2,%3}, [%4];\n"
        : "=r"(r[0]), "=r"(r[1]), "=r"(r[2]), "=r"(r[3]) : "r"(addr));
}
__device__ __forceinline__ void ldsm4t(uint32_t* r, uint32_t addr) {
    asm volatile("ldmatrix.sync.aligned.m8n8.x4.trans.shared.b16 {%0,%1,%2,%3}, [%4];\n"
        : "=r"(r[0]), "=r"(r[1]), "=r"(r[2]), "=r"(r[3]) : "r"(addr));
}
__device__ __forceinline__ void mma_f16(float* c, const uint32_t* a,
                                        uint32_t b0, uint32_t b1) {
    asm volatile(
        "mma.sync.aligned.m16n8k16.row.col.f32.f16.f16.f32 "
        "{%0,%1,%2,%3}, {%4,%5,%6,%7}, {%8,%9}, {%0,%1,%2,%3};\n"
        : "+f"(c[0]), "+f"(c[1]), "+f"(c[2]), "+f"(c[3])
        : "r"(a[0]), "r"(a[1]), "r"(a[2]), "r"(a[3]), "r"(b0), "r"(b1));
}
__device__ __forceinline__ uint32_t packh2(__half a, __half b) {
    return (uint32_t)__half_as_ushort(a) | ((uint32_t)__half_as_ushort(b) << 16);
}
__device__ __forceinline__ void cp16(uint32_t saddr, const void* gptr) {
    asm volatile("cp.async.cg.shared.global [%0], [%1], 16;" :: "r"(saddr), "l"(gptr));
}
#define CP_COMMIT() asm volatile("cp.async.commit_group;" ::: "memory")
#define CP_WAIT0()  asm volatile("cp.async.wait_group 0;" ::: "memory")

// ---------------- 1) fold BN + fp16 weight plane -------------------------------
__global__ void fold_kernel(
    const float* __restrict__ Wq, const float* __restrict__ gq, const float* __restrict__ bq,
    const float* __restrict__ mq, const float* __restrict__ vq,
    const float* __restrict__ Wkv, const float* __restrict__ gkv, const float* __restrict__ bkv,
    const float* __restrict__ mkv, const float* __restrict__ vkv,
    const float* __restrict__ Wp, const float* __restrict__ gp, const float* __restrict__ bp,
    const float* __restrict__ mp, const float* __restrict__ vp)
{
    int t = blockIdx.x * blockDim.x + threadIdx.x;
    int stride = gridDim.x * blockDim.x;
    const float eps = 1e-5f;
    for (int i = t; i < MQ; i += stride) {
        float s = gq[i] * rsqrtf(vq[i] + eps); g_bq[i] = bq[i] - mq[i] * s;
    }
    for (int i = t; i < CIN; i += stride) {
        float s = gp[i] * rsqrtf(vp[i] + eps); g_bp[i] = bp[i] - mp[i] * s;
    }
    for (int i = t; i < DHEAD; i += stride) {
        float s = gkv[i] * rsqrtf(vkv[i] + eps); g_bkv[i] = bkv[i] - mkv[i] * s;
    }
    for (int i = t; i < DHEAD * CIN; i += stride) {
        int o = i / CIN; g_Wkv[i] = Wkv[i] * gkv[o] * rsqrtf(vkv[o] + eps);
    }
    for (int i = t; i < MQ * CIN; i += stride) {
        int m = i >> 8;
        g_WH[0][i] = __float2half_rn(Wq[i] * gq[m] * rsqrtf(vq[m] + eps));
        g_WH[1][i] = __float2half_rn(Wp[i] * gp[m] * rsqrtf(vp[m] + eps));
    }
}

// ---------------- 2) KV projection + fp16 input copy -----------------------------
__global__ __launch_bounds__(256) void kv_kernel(const float* __restrict__ X)
{
    __shared__ __align__(16) float Ws[CIN][DHEAD];
    __shared__ float bs[DHEAD];
    int t = threadIdx.x;
    for (int i = t; i < DHEAD * CIN; i += 256) {
        int m = i / CIN, k = i % CIN;
        Ws[k][m] = g_Wkv[i];
    }
    if (t < DHEAD) bs[t] = g_bkv[t];
    __syncthreads();

    int b = blockIdx.y;
    int n = blockIdx.x * 256 + t;
    const float* x = X + (size_t)b * CIN * HWN + n;
    __half* xin = g_XIN + (size_t)b * CIN * HWN + n;

    unsigned long long acc[16];
#pragma unroll
    for (int j = 0; j < 16; j++) PACKF2(acc[j], bs[2 * j], bs[2 * j + 1]);

#pragma unroll 4
    for (int k = 0; k < CIN; k++) {
        float xv = x[(size_t)k * HWN];
        xin[(size_t)k * HWN] = __float2half_rn(xv);
        unsigned long long xp; PACKF2(xp, xv, xv);
        const ulonglong2* wr = reinterpret_cast<const ulonglong2*>(&Ws[k][0]);
#pragma unroll
        for (int j = 0; j < 8; j++) {
            ulonglong2 w = wr[j];
            FMAF2(acc[2 * j],     w.x, xp);
            FMAF2(acc[2 * j + 1], w.y, xp);
        }
    }
    float* y = g_KV + (size_t)b * DHEAD * HWN + n;
#pragma unroll
    for (int j = 0; j < 16; j++) {
        float lo, hi; UNPACKF2(lo, hi, acc[j]);
        y[(size_t)(2 * j) * HWN] = lo;
        y[(size_t)(2 * j + 1) * HWN] = hi;
    }
}

// ---------------- 3) row softmax stats + zero ctxT -------------------------------
__global__ __launch_bounds__(256) void rowstats_kernel()
{
    __shared__ float red[8];
    int d = blockIdx.x, b = blockIdx.y, t = threadIdx.x;
    int w = t >> 5, l = t & 31;
    if (t < 32) g_ctxT[b * 1024 + d * 32 + t] = 0.0f;
    const float* row = g_KV + ((size_t)b * DHEAD + d) * HWN;

    float mx = -1e30f;
    for (int n = t; n < HWN; n += 256) mx = fmaxf(mx, row[n]);
#pragma unroll
    for (int o = 16; o > 0; o >>= 1) mx = fmaxf(mx, __shfl_xor_sync(~0u, mx, o));
    if (l == 0) red[w] = mx;
    __syncthreads();
    mx = red[0];
#pragma unroll
    for (int j = 1; j < 8; j++) mx = fmaxf(mx, red[j]);
    __syncthreads();

    float s = 0.0f;
    for (int n = t; n < HWN; n += 256) s += __expf(row[n] - mx);
#pragma unroll
    for (int o = 16; o > 0; o >>= 1) s += __shfl_xor_sync(~0u, s, o);
    if (l == 0) red[w] = s;
    __syncthreads();
    if (t == 0) {
        float tot = 0.0f;
#pragma unroll
        for (int j = 0; j < 8; j++) tot += red[j];
        g_rm[b * DHEAD + d] = mx;
        g_rs[b * DHEAD + d] = tot;
    }
}

// ---------------- 4) ctxT ----------------------------------------------------------
__global__ __launch_bounds__(256) void ctx_kernel()
{
    __shared__ float kvs[DHEAD][129];
    __shared__ float ps [DHEAD][129];
    __shared__ float ms[DHEAD], ssi[DHEAD];

    int b = blockIdx.y, t = threadIdx.x;
    if (t < DHEAD) { ms[t] = g_rm[b * DHEAD + t]; ssi[t] = 1.0f / g_rs[b * DHEAD + t]; }
    __syncthreads();

    int n0 = blockIdx.x * 128;
    for (int i = t; i < DHEAD * 128; i += 256) {
        int r = i >> 7, nn = i & 127;
        float v = g_KV[((size_t)b * DHEAD + r) * HWN + n0 + nn];
        kvs[r][nn] = v;
        ps [r][nn] = __expf(v - ms[r]) * ssi[r];
    }
    __syncthreads();

    int d = t & 31, e0 = (t >> 5) * 4;
    float acc[4] = {0.f, 0.f, 0.f, 0.f};
#pragma unroll 4
    for (int nn = 0; nn < 128; nn++) {
        float kd = kvs[d][nn];
#pragma unroll
        for (int j = 0; j < 4; j++) acc[j] += ps[e0 + j][nn] * kd;
    }
#pragma unroll
    for (int j = 0; j < 4; j++)
        atomicAdd(&g_ctxT[b * 1024 + d * 32 + (e0 + j)], acc[j]);
}

// ---------------- 5) qattn: pipelined GEMM0 + softmax + ctxT-matvec + relu --------
// 256 threads (8 warps), tile M=128 x N=128, grid (32 nt, 2 mt, 16 b).
// Both W and X tiles via cp.async fp16, 2-stage double buffer. 2 CTAs/SM.
#define QA_WS0  0
#define QA_WS1  18432
#define QA_XS0  36864
#define QA_XS1  54272
#define QA_CSH  71680
#define QA_CSL  74240
#define QA_BIAS 76800
#define QA_SMEM 77312
#define QA_Q    0          /* sQ (34816 B) reuses W stages after mainloop */

__global__ void __launch_bounds__(256, 2) qattn_kernel()
{
    extern __shared__ __align__(16) char smem[];
    __half* sCh = reinterpret_cast<__half*>(smem + QA_CSH);
    __half* sCl = reinterpret_cast<__half*>(smem + QA_CSL);
    float* sBias = reinterpret_cast<float*>(smem + QA_BIAS);
    __half* sQ  = reinterpret_cast<__half*>(smem + QA_Q);
    uint32_t sb = (uint32_t)__cvta_generic_to_shared(smem);

    int t = threadIdx.x, lane = t & 31, wid = t >> 5;
    int wm = wid >> 1, wn = wid & 1;
    int nt = blockIdx.x, mt = blockIdx.y, b = blockIdx.z;
    int n0 = nt * 128, m0 = mt * 128;
    const __half* W = g_WH[0] + (size_t)m0 * CIN;
    const __half* Xin = g_XIN + (size_t)b * CIN * HWN + n0;

    // preload ctxT (hi/lo fp16, stride 40) and bias for this M tile
    for (int i = t; i < 1024; i += 256) {
        int d = i >> 5, e = i & 31;
        float f = g_ctxT[b * 1024 + i];
        __half h = __float2half_rn(f);
        sCh[d * 40 + e] = h;
        sCl[d * 40 + e] = __float2half_rn(f - __half2float(h));
    }
    if (t < 128) sBias[t] = g_bq[m0 + t];

    // ---- prologue: chunk 0 (W: 128x64, X: 64x128) ----
#pragma unroll
    for (int i = 0; i < 4; i++) {
        int j = t + i * 256;
        int row = j >> 3, seg = j & 7;
        cp16(sb + QA_WS0 + (uint32_t)(row * 72 + seg * 8) * 2,
             W + (size_t)row * CIN + seg * 8);
    }
#pragma unroll
    for (int i = 0; i < 4; i++) {
        int j = t + i * 256;
        int k = j >> 4, seg = j & 15;
        cp16(sb + QA_XS0 + (uint32_t)(k * 136 + seg * 8) * 2,
             Xin + (size_t)k * HWN + seg * 8);
    }
    CP_COMMIT();
    CP_WAIT0();
    __syncthreads();

    float acc[2][8][4];
#pragma unroll
    for (int i = 0; i < 2; i++)
#pragma unroll
        for (int j = 0; j < 8; j++)
#pragma unroll
            for (int k = 0; k < 4; k++) acc[i][j][k] = 0.0f;

    for (int c = 0; c < 4; c++) {
        int s = c & 1;
        uint32_t wbase = sb + (s ? QA_WS1 : QA_WS0);
        uint32_t xbase = sb + (s ? QA_XS1 : QA_XS0);
        if (c < 3) {
            int k0n = (c + 1) * 64;
            uint32_t wdst = sb + (s ? QA_WS0 : QA_WS1);
            uint32_t xdst = sb + (s ? QA_XS0 : QA_XS1);
#pragma unroll
            for (int i = 0; i < 4; i++) {
                int j = t + i * 256;
                int row = j >> 3, seg = j & 7;
                cp16(wdst + (uint32_t)(row * 72 + seg * 8) * 2,
                     W + (size_t)row * CIN + k0n + seg * 8);
            }
#pragma unroll
            for (int i = 0; i < 4; i++) {
                int j = t + i * 256;
                int k = j >> 4, seg = j & 15;
                cp16(xdst + (uint32_t)(k * 136 + seg * 8) * 2,
                     Xin + (size_t)(k0n + k) * HWN + seg * 8);
            }
            CP_COMMIT();
        }
#pragma unroll
        for (int ks = 0; ks < 4; ks++) {
            int kk = ks * 16;
            uint32_t ah[2][4];
#pragma unroll
            for (int mf = 0; mf < 2; mf++) {
                int row = wm * 32 + mf * 16 + (lane & 15);
                int col = kk + (lane >> 4) * 8;
                ldsm4(ah[mf], wbase + (uint32_t)(row * 72 + col) * 2);
            }
#pragma unroll
            for (int r = 0; r < 4; r++) {
                int kr = kk + (lane & 15);
                int coln = wn * 64 + r * 16 + (lane >> 4) * 8;
                uint32_t bh[4];
                ldsm4t(bh, xbase + (uint32_t)(kr * 136 + coln) * 2);
#pragma unroll
                for (int mf = 0; mf < 2; mf++) {
                    mma_f16(acc[mf][r * 2],     ah[mf], bh[0], bh[1]);
                    mma_f16(acc[mf][r * 2 + 1], ah[mf], bh[2], bh[3]);
                }
            }
        }
        if (c < 3) {
            CP_WAIT0();
            __syncthreads();
        }
    }
    __syncthreads();   // all compute done before sQ overwrites W stages

    // ---- fused epilogue: bias + per-column head softmax (head = mt*4 + wm) ----
    {
        int r0 = wm * 32 + (lane >> 2);
        float bv[4] = { sBias[r0], sBias[r0 + 8], sBias[r0 + 16], sBias[r0 + 24] };
#pragma unroll
        for (int mf = 0; mf < 2; mf++)
#pragma unroll
            for (int nf = 0; nf < 8; nf++)
#pragma unroll
                for (int k = 0; k < 4; k++)
                    acc[mf][nf][k] += bv[mf * 2 + (k >> 1)];
    }
#pragma unroll
    for (int nf = 0; nf < 8; nf++) {
#pragma unroll
        for (int p = 0; p < 2; p++) {
            float m = fmaxf(fmaxf(acc[0][nf][p], acc[0][nf][p + 2]),
                            fmaxf(acc[1][nf][p], acc[1][nf][p + 2]));
            m = fmaxf(m, __shfl_xor_sync(~0u, m, 4));
            m = fmaxf(m, __shfl_xor_sync(~0u, m, 8));
            m = fmaxf(m, __shfl_xor_sync(~0u, m, 16));
            float e00 = __expf(acc[0][nf][p] - m);
            float e01 = __expf(acc[0][nf][p + 2] - m);
            float e10 = __expf(acc[1][nf][p] - m);
            float e11 = __expf(acc[1][nf][p + 2] - m);
            float s = e00 + e01 + e10 + e11;
            s += __shfl_xor_sync(~0u, s, 4);
            s += __shfl_xor_sync(~0u, s, 8);
            s += __shfl_xor_sync(~0u, s, 16);
            float inv = 1.0f / s;
            acc[0][nf][p]     = e00 * inv;
            acc[0][nf][p + 2] = e01 * inv;
            acc[1][nf][p]     = e10 * inv;
            acc[1][nf][p + 2] = e11 * inv;
        }
    }
    // stage softmaxed q (fp16, stride 136) — warp-local block only
#pragma unroll
    for (int mf = 0; mf < 2; mf++)
#pragma unroll
        for (int nf = 0; nf < 8; nf++) {
            int row = wm * 32 + mf * 16 + (lane >> 2);
            int col = wn * 64 + nf * 8 + (lane & 3) * 2;
            *reinterpret_cast<uint32_t*>(sQ + row * 136 + col) =
                packh2(__float2half_rn(acc[mf][nf][0]), __float2half_rn(acc[mf][nf][1]));
            *reinterpret_cast<uint32_t*>(sQ + (row + 8) * 136 + col) =
                packh2(__float2half_rn(acc[mf][nf][2]), __float2half_rn(acc[mf][nf][3]));
        }
    __syncwarp();

    // att = ctxT @ q  (ctxT hi/lo 2-pass, q single; ctxT shared across heads)
    float att[2][8][4];
#pragma unroll
    for (int i = 0; i < 2; i++)
#pragma unroll
        for (int j = 0; j < 8; j++)
#pragma unroll
            for (int k = 0; k < 4; k++) att[i][j][k] = 0.0f;

#pragma unroll
    for (int kf = 0; kf < 2; kf++) {
        uint32_t ach[2][4], acl[2][4];
#pragma unroll
        for (int mf = 0; mf < 2; mf++) {
            int row = mf * 16 + (lane & 15);
            int col = kf * 16 + (lane >> 4) * 8;
            uint32_t a_addr = sb + QA_CSH + (uint32_t)(row * 40 + col) * 2;
            ldsm4(ach[mf], a_addr);
            ldsm4(acl[mf], a_addr + (QA_CSL - QA_CSH));
        }
#pragma unroll
        for (int r = 0; r < 4; r++) {
            int kr = wm * 32 + kf * 16 + (lane & 15);
            int coln = wn * 64 + r * 16 + (lane >> 4) * 8;
            uint32_t qb[4];
            ldsm4t(qb, sb + QA_Q + (uint32_t)(kr * 136 + coln) * 2);
#pragma unroll
            for (int mf = 0; mf < 2; mf++) {
                mma_f16(att[mf][r * 2],     ach[mf], qb[0], qb[1]);
                mma_f16(att[mf][r * 2 + 1], ach[mf], qb[2], qb[3]);
                mma_f16(att[mf][r * 2],     acl[mf], qb[0], qb[1]);
                mma_f16(att[mf][r * 2 + 1], acl[mf], qb[2], qb[3]);
            }
        }
    }

    // relu + fp16 store (global rows m0 + local row)
#pragma unroll
    for (int mf = 0; mf < 2; mf++)
#pragma unroll
        for (int nf = 0; nf < 8; nf++) {
            int row = m0 + wm * 32 + mf * 16 + (lane >> 2);
            int col = n0 + wn * 64 + nf * 8 + (lane & 3) * 2;
            float v0 = fmaxf(att[mf][nf][0], 0.f), v1 = fmaxf(att[mf][nf][1], 0.f);
            float v2 = fmaxf(att[mf][nf][2], 0.f), v3 = fmaxf(att[mf][nf][3], 0.f);
            *reinterpret_cast<uint32_t*>(&g_XF[((size_t)(b * MQ) + row) * HWN + col]) =
                packh2(__float2half_rn(v0), __float2half_rn(v1));
            *reinterpret_cast<uint32_t*>(&g_XF[((size_t)(b * MQ) + row + 8) * HWN + col]) =
                packh2(__float2half_rn(v2), __float2half_rn(v3));
        }
}

// ---------------- 6) proj: pipelined single-pass fp16 GEMM ------------------------
// 256 threads, tile M=128 x N=128, grid (32 nt, 2 mt, 16 b). 2 CTAs/SM.
#define G1_WS0  0
#define G1_WS1  18432
#define G1_XS0  36864
#define G1_XS1  54272
#define G1_SMEM 71680

__global__ void __launch_bounds__(256, 2) proj_kernel(float* __restrict__ out)
{
    extern __shared__ __align__(16) char smem[];
    uint32_t sb = (uint32_t)__cvta_generic_to_shared(smem);

    int t = threadIdx.x, lane = t & 31, wid = t >> 5;
    int wm = wid >> 1, wn = wid & 1;
    int nt = blockIdx.x, mt = blockIdx.y, b = blockIdx.z;
    int n0 = nt * 128, m0 = mt * 128;
    const __half* W = g_WH[1] + (size_t)m0 * CIN;
    const __half* Xin = g_XF + (size_t)b * MQ * HWN + n0;

    // prologue: chunk 0
#pragma unroll
    for (int i = 0; i < 4; i++) {
        int j = t + i * 256;
        int row = j >> 3, seg = j & 7;
        cp16(sb + G1_WS0 + (uint32_t)(row * 72 + seg * 8) * 2,
             W + (size_t)row * CIN + seg * 8);
    }
#pragma unroll
    for (int i = 0; i < 4; i++) {
        int j = t + i * 256;
        int k = j >> 4, seg = j & 15;
        cp16(sb + G1_XS0 + (uint32_t)(k * 136 + seg * 8) * 2,
             Xin + (size_t)k * HWN + seg * 8);
    }
    CP_COMMIT();
    CP_WAIT0();
    __syncthreads();

    float acc[2][8][4];
#pragma unroll
    for (int i = 0; i < 2; i++)
#pragma unroll
        for (int j = 0; j < 8; j++)
#pragma unroll
            for (int k = 0; k < 4; k++) acc[i][j][k] = 0.0f;

    for (int c = 0; c < 4; c++) {
        int s = c & 1;
        uint32_t wbase = sb + (s ? G1_WS1 : G1_WS0);
        uint32_t xbase = sb + (s ? G1_XS1 : G1_XS0);
        if (c < 3) {
            int k0n = (c + 1) * 64;
            uint32_t wdst = sb + (s ? G1_WS0 : G1_WS1);
            uint32_t xdst = sb + (s ? G1_XS0 : G1_XS1);
#pragma unroll
            for (int i = 0; i < 4; i++) {
                int j = t + i * 256;
                int row = j >> 3, seg = j & 7;
                cp16(wdst + (uint32_t)(row * 72 + seg * 8) * 2,
                     W + (size_t)row * CIN + k0n + seg * 8);
            }
#pragma unroll
            for (int i = 0; i < 4; i++) {
                int j = t + i * 256;
                int k = j >> 4, seg = j & 15;
                cp16(xdst + (uint32_t)(k * 136 + seg * 8) * 2,
                     Xin + (size_t)(k0n + k) * HWN + seg * 8);
            }
            CP_COMMIT();
        }
#pragma unroll
        for (int ks = 0; ks < 4; ks++) {
            int kk = ks * 16;
            uint32_t ah[2][4];
#pragma unroll
            for (int mf = 0; mf < 2; mf++) {
                int row = wm * 32 + mf * 16 + (lane & 15);
                int col = kk + (lane >> 4) * 8;
                ldsm4(ah[mf], wbase + (uint32_t)(row * 72 + col) * 2);
            }
#pragma unroll
            for (int r = 0; r < 4; r++) {
                int kr = kk + (lane & 15);
                int coln = wn * 64 + r * 16 + (lane >> 4) * 8;
                uint32_t bh[4];
                ldsm4t(bh, xbase + (uint32_t)(kr * 136 + coln) * 2);
#pragma unroll
                for (int mf = 0; mf < 2; mf++) {
                    mma_f16(acc[mf][r * 2],     ah[mf], bh[0], bh[1]);
                    mma_f16(acc[mf][r * 2 + 1], ah[mf], bh[2], bh[3]);
                }
            }
        }
        if (c < 3) {
            CP_WAIT0();
            __syncthreads();
        }
    }

    int r0 = m0 + wm * 32 + (lane >> 2);
    float bv[4] = { g_bp[r0], g_bp[r0 + 8], g_bp[r0 + 16], g_bp[r0 + 24] };
#pragma unroll
    for (int mf = 0; mf < 2; mf++)
#pragma unroll
        for (int nf = 0; nf < 8; nf++) {
            int row = m0 + wm * 32 + mf * 16 + (lane >> 2);
            int col = n0 + wn * 64 + nf * 8 + (lane & 3) * 2;
            float bb0 = bv[mf * 2], bb1 = bv[mf * 2 + 1];
            *reinterpret_cast<float2*>(&out[((size_t)(b * MQ) + row) * HWN + col]) =
                make_float2(acc[mf][nf][0] + bb0, acc[mf][nf][1] + bb0);
            *reinterpret_cast<float2*>(&out[((size_t)(b * MQ) + row + 8) * HWN + col]) =
                make_float2(acc[mf][nf][2] + bb1, acc[mf][nf][3] + bb1);
        }
}

// ---------------- launch ------------------------------------------------------------
extern "C" void kernel_launch(void* const* d_in, const int* in_sizes, int n_in,
                              void* d_out, int out_size)
{
    const float* input = (const float*)d_in[0];
    const float* Wq  = (const float*)d_in[2];
    const float* gq  = (const float*)d_in[3];
    const float* bq  = (const float*)d_in[4];
    const float* mq  = (const float*)d_in[5];
    const float* vq  = (const float*)d_in[6];
    const float* Wkv = (const float*)d_in[7];
    const float* gkv = (const float*)d_in[8];
    const float* bkv = (const float*)d_in[9];
    const float* mkv = (const float*)d_in[10];
    const float* vkv = (const float*)d_in[11];
    const float* Wp  = (const float*)d_in[12];
    const float* gp  = (const float*)d_in[13];
    const float* bp  = (const float*)d_in[14];
    const float* mp  = (const float*)d_in[15];
    const float* vp  = (const float*)d_in[16];
    float* out = (float*)d_out;

    cudaFuncSetAttribute(qattn_kernel, cudaFuncAttributeMaxDynamicSharedMemorySize, QA_SMEM);
    cudaFuncSetAttribute(proj_kernel, cudaFuncAttributeMaxDynamicSharedMemorySize, G1_SMEM);

    fold_kernel<<<64, 256>>>(Wq, gq, bq, mq, vq,
                             Wkv, gkv, bkv, mkv, vkv,
                             Wp, gp, bp, mp, vp);
    kv_kernel<<<dim3(HWN / 256, BATCH), 256>>>(input);
    rowstats_kernel<<<dim3(DHEAD, BATCH), 256>>>();
    ctx_kernel<<<dim3(HWN / 128, BATCH), 256>>>();
    qattn_kernel<<<dim3(HWN / 128, 2, BATCH), 256, QA_SMEM>>>();
    proj_kernel<<<dim3(HWN / 128, 2, BATCH), 256, G1_SMEM>>>(out);
}